// round 8
// baseline (speedup 1.0000x reference)
#include <cuda_runtime.h>
#include <cuda_bf16.h>
#include <math.h>
#include <stdint.h>

// ---------------------------------------------------------------------------
// EmbedMatcher on GB300 (sm_103 plain PTX -> mma.sync bf16x3 tensor cores).
//  - Gate-interleaved weight packing (col = unit*4 + gate) lets the LSTM cell
//    update run inside the GEMM epilogue (shfl-pair gate exchange): no ACC
//    buffer, no separate cell kernels.
//  - Dead-gate elimination (N 2048->1024) + rank-1 support factorization.
//  - Templated M-tile (128 or 64) so every GEMM fills >=128 CTAs.
//  - One merged weight-split kernel; float4 vectorized gather.
// ---------------------------------------------------------------------------

__device__ __forceinline__ uint32_t smem_u32(const void* p) {
    uint32_t a;
    asm("{ .reg .u64 t; cvta.to.shared.u64 t, %1; cvt.u32.u64 %0, t; }"
        : "=r"(a) : "l"(p));
    return a;
}

// ================= fp32 scratch =================
constexpr size_t N_BUFS = 16UL * 256;
constexpr size_t N_INVQ = 8192;
constexpr size_t N_INVS = 64;
constexpr size_t N_QNB  = 4096UL * 256;
constexpr size_t N_ZQ   = 4096UL * 256;
constexpr size_t N_QG   = 4096UL * 256;
constexpr size_t N_SG   = 256;
constexpr size_t N_SN   = 256;
constexpr size_t N_XW   = 4096UL * 1024;
constexpr size_t N_GB0  = 1024;
constexpr size_t N_GB1  = 1024;
constexpr size_t N_C    = 4096UL * 256;
constexpr size_t N_H    = 4096UL * 256;

constexpr size_t O_BUFS = 0;
constexpr size_t O_INVQ = O_BUFS + N_BUFS;
constexpr size_t O_INVS = O_INVQ + N_INVQ;
constexpr size_t O_QNB  = O_INVS + N_INVS;
constexpr size_t O_ZQ   = O_QNB  + N_QNB;
constexpr size_t O_QG   = O_ZQ   + N_ZQ;
constexpr size_t O_SG   = O_QG   + N_QG;
constexpr size_t O_SN   = O_SG   + N_SG;
constexpr size_t O_XW   = O_SN   + N_SN;
constexpr size_t O_GB0  = O_XW   + N_XW;
constexpr size_t O_GB1  = O_GB0  + N_GB0;
constexpr size_t O_C    = O_GB1  + N_GB1;
constexpr size_t O_H    = O_C    + N_C;
constexpr size_t SCRATCH_TOTAL = O_H + N_H;
__device__ float g_scratch[SCRATCH_TOTAL];

// ================= bf16 split scratch =================
constexpr size_t B_BUFQH = 0;
constexpr size_t B_BUFQL = B_BUFQH + 8192UL * 256;
constexpr size_t B_QNBH  = B_BUFQL + 8192UL * 256;
constexpr size_t B_QNBL  = B_QNBH  + 4096UL * 256;
constexpr size_t B_HQH   = B_QNBL  + 4096UL * 256;
constexpr size_t B_HQL   = B_HQH   + 4096UL * 512;
constexpr size_t B_QGH   = B_HQL   + 4096UL * 512;
constexpr size_t B_QGL   = B_QGH   + 4096UL * 256;
constexpr size_t B_HH    = B_QGL   + 4096UL * 256;
constexpr size_t B_HL    = B_HH    + 4096UL * 256;
constexpr size_t B_GWH   = B_HL    + 4096UL * 256;
constexpr size_t B_GWL   = B_GWH   + 128UL * 256;
constexpr size_t B_P1H   = B_GWL   + 128UL * 256;
constexpr size_t B_P1L   = B_P1H   + 512UL * 256;
constexpr size_t B_P2H   = B_P1L   + 512UL * 256;
constexpr size_t B_P2L   = B_P2H   + 256UL * 512;
constexpr size_t B_WIHH  = B_P2L   + 256UL * 512;
constexpr size_t B_WIHL  = B_WIHH  + 1024UL * 256;
constexpr size_t B_WHHH  = B_WIHL  + 1024UL * 256;
constexpr size_t B_WHHL  = B_WHHH  + 1024UL * 256;
constexpr size_t BF_TOTAL = B_WHHL + 1024UL * 256;
__device__ __align__(128) __nv_bfloat16 g_bf[BF_TOTAL];

// ================= helpers =================
__device__ __forceinline__ float sigf(float x) { return 1.0f / (1.0f + expf(-x)); }

__device__ __forceinline__ float block_sum256(float v, float* sbuf) {
    int t = threadIdx.x;
    sbuf[t] = v;
    __syncthreads();
    #pragma unroll
    for (int s = 128; s > 0; s >>= 1) {
        if (t < s) sbuf[t] += sbuf[t + s];
        __syncthreads();
    }
    float r = sbuf[0];
    __syncthreads();
    return r;
}

// ================= fused gather, float4 loads ================================
__global__ void gather_all_kernel(const int* __restrict__ qlc, const int* __restrict__ qld,
                                  const int* __restrict__ qrc, const int* __restrict__ qrd,
                                  const int* __restrict__ slc, const int* __restrict__ sld,
                                  const int* __restrict__ src_, const int* __restrict__ srd,
                                  const float* __restrict__ emb,
                                  __nv_bfloat16* __restrict__ bqh, __nv_bfloat16* __restrict__ bql,
                                  float* __restrict__ invq,
                                  float* __restrict__ bufs, float* __restrict__ invs)
{
    __shared__ int sc[128];
    __shared__ float4 red[2][4][32];
    int b = blockIdx.x;
    const int* conn; const int* deg; int r, row; bool isq;
    float* inv;
    if (b < 4096)      { r = b;        conn = qlc;  deg = qld; inv = invq; row = 2 * r;     isq = true;  }
    else if (b < 8192) { r = b - 4096; conn = qrc;  deg = qrd; inv = invq; row = 2 * r + 1; isq = true;  }
    else if (b < 8197) { r = b - 8192; conn = slc;  deg = sld; inv = invs; row = 2 * r;     isq = false; }
    else               { r = b - 8197; conn = src_; deg = srd; inv = invs; row = 2 * r + 1; isq = false; }
    int t = threadIdx.x;  // 128
    int w = t >> 5, l = t & 31;
    sc[t] = conn[r * 128 + t];
    __syncthreads();
    float4 a0 = make_float4(0.f, 0.f, 0.f, 0.f);
    float4 a1 = make_float4(0.f, 0.f, 0.f, 0.f);
    #pragma unroll 4
    for (int i = 0; i < 16; i++) {
        int n = w * 16 + i;
        float4 v0 = __ldg((const float4*)(emb + (size_t)sc[2 * n]     * 128) + l);
        float4 v1 = __ldg((const float4*)(emb + (size_t)sc[2 * n + 1] * 128) + l);
        a0.x += v0.x; a0.y += v0.y; a0.z += v0.z; a0.w += v0.w;
        a1.x += v1.x; a1.y += v1.y; a1.z += v1.z; a1.w += v1.w;
    }
    red[0][w][l] = a0;
    red[1][w][l] = a1;
    __syncthreads();
    if (t < 64) {
        int which = t >> 5, ll = t & 31;
        float4 p0 = red[which][0][ll], p1 = red[which][1][ll];
        float4 p2 = red[which][2][ll], p3 = red[which][3][ll];
        float s[4];
        s[0] = p0.x + p1.x + p2.x + p3.x;
        s[1] = p0.y + p1.y + p2.y + p3.y;
        s[2] = p0.z + p1.z + p2.z + p3.z;
        s[3] = p0.w + p1.w + p2.w + p3.w;
        size_t base = (size_t)row * 256 + which * 128 + ll * 4;
        if (isq) {
            #pragma unroll
            for (int j = 0; j < 4; j++) {
                __nv_bfloat16 h = __float2bfloat16(s[j]);
                bqh[base + j] = h;
                bql[base + j] = __float2bfloat16(s[j] - __bfloat162float(h));
            }
        } else {
            #pragma unroll
            for (int j = 0; j < 4; j++) bufs[base + j] = s[j];
        }
    }
    if (t == 0) inv[row] = 1.0f / (float)max(deg[r], 1);
}

// ================= merged weight splits + gb0 ================================
// blocks: [0,128) gcn | [128,640) p1 | [640,1152) p2 | [1152,2176) w_ih packed
//         [2176,3200) w_hh packed | 3200 gb0
__global__ void split_all_kernel(const float* __restrict__ gcn_w,
                                 const float* __restrict__ p1w,
                                 const float* __restrict__ p2w,
                                 const float* __restrict__ w_ih,
                                 const float* __restrict__ w_hh,
                                 const float* __restrict__ b_ih,
                                 const float* __restrict__ b_hh,
                                 __nv_bfloat16* __restrict__ gwh, __nv_bfloat16* __restrict__ gwl,
                                 __nv_bfloat16* __restrict__ p1h, __nv_bfloat16* __restrict__ p1l,
                                 __nv_bfloat16* __restrict__ p2h, __nv_bfloat16* __restrict__ p2l,
                                 __nv_bfloat16* __restrict__ wih, __nv_bfloat16* __restrict__ wil,
                                 __nv_bfloat16* __restrict__ whh, __nv_bfloat16* __restrict__ whl,
                                 float* __restrict__ gb0)
{
    int b = blockIdx.x, t = threadIdx.x;
    if (b == 3200) {
        #pragma unroll
        for (int k = 0; k < 4; k++) {
            int col = k * 256 + t;
            int g = col & 3, u = col >> 2;
            gb0[col] = b_ih[g * 512 + u] + b_hh[g * 512 + u];
        }
        return;
    }
    float v;
    __nv_bfloat16 *hi, *lo;
    int idx;
    if (b < 128)       { idx = b * 256 + t;          v = gcn_w[idx]; hi = gwh; lo = gwl; }
    else if (b < 640)  { idx = (b - 128) * 256 + t;  v = p1w[idx];   hi = p1h; lo = p1l; }
    else if (b < 1152) { idx = (b - 640) * 256 + t;  v = p2w[idx];   hi = p2h; lo = p2l; }
    else {
        const float* W; int ldw;
        if (b < 2176) { idx = (b - 1152) * 256 + t; W = w_ih; ldw = 256; hi = wih; lo = wil; }
        else          { idx = (b - 2176) * 256 + t; W = w_hh; ldw = 512; hi = whh; lo = whl; }
        int orow = idx >> 8, c = idx & 255;
        int u = orow >> 2, g = orow & 3;           // packed col = u*4+g
        v = W[(size_t)(g * 512 + u) * ldw + c];
    }
    __nv_bfloat16 h = __float2bfloat16(v);
    hi[idx] = h;
    lo[idx] = __float2bfloat16(v - __bfloat162float(h));
}

// ================= gb1 = gb0 + rvec (packed, live rows only) =================
__global__ void gb1_kernel(const float* __restrict__ w_hh,
                           const float* __restrict__ sg,
                           const float* __restrict__ gb0,
                           float* __restrict__ gb1)
{
    int col = blockIdx.x * 256 + threadIdx.x;  // 1024
    int g = col & 3, u = col >> 2;
    const float* w = w_hh + (size_t)(g * 512 + u) * 512 + 256;
    float s = 0.0f;
    #pragma unroll 8
    for (int k = 0; k < 256; k++) s += w[k] * sg[k];
    gb1[col] = gb0[col] + s;
}

// ================= unified mma.sync bf16x3 GEMM ==============================
// C(MxN) = A(MxK) @ B(NxK)^T; bf16x3 segments (Ah,Bh)|(Ah,Bl)|(Al,Bh).
// 256 threads, 8 warps (2m x 4n). MI = m16-frags per warp (4 -> 128-row CTA,
// 2 -> 64-row CTA). N tile fixed 128. 2-stage cp.async pipeline.
enum { EPI_RELU = 1, EPI_RES = 2, EPI_NB = 3, EPI_CELL0 = 4, EPI_CELL = 5 };

__device__ __forceinline__ void cp16(uint32_t daddr, const void* g) {
    asm volatile("cp.async.cg.shared.global [%0], [%1], 16;" :: "r"(daddr), "l"(g));
}

template <int MT>
__device__ __forceinline__ void stage_load(char* sa, char* sb,
                                           const __nv_bfloat16* __restrict__ Asrc,
                                           const __nv_bfloat16* __restrict__ Bsrc,
                                           int lda, int ldb, int bm, int bn,
                                           int koff, int tid)
{
    #pragma unroll
    for (int i = 0; i < MT / 32; i++) {
        int idx = i * 256 + tid;
        int row = idx >> 3, ch = idx & 7;
        uint32_t off = (uint32_t)(row * 128 + ch * 16);
        uint32_t sw  = off ^ ((off >> 3) & 0x70);
        cp16(smem_u32(sa + sw), Asrc + (size_t)(bm + row) * lda + koff + ch * 8);
    }
    #pragma unroll
    for (int i = 0; i < 4; i++) {
        int idx = i * 256 + tid;
        int row = idx >> 3, ch = idx & 7;
        uint32_t off = (uint32_t)(row * 128 + ch * 16);
        uint32_t sw  = off ^ ((off >> 3) & 0x70);
        cp16(smem_u32(sb + sw), Bsrc + (size_t)(bn + row) * ldb + koff + ch * 8);
    }
}

template <int EPI>
__device__ __forceinline__ void cell_store(int r, int u,
                                           float gi, float gf, float gg, float go,
                                           float* __restrict__ cvec,
                                           const float* __restrict__ qg,
                                           float* __restrict__ hout,
                                           __nv_bfloat16* __restrict__ outh,
                                           __nv_bfloat16* __restrict__ outl)
{
    size_t idx = (size_t)r * 256 + u;
    float cp = (EPI == EPI_CELL) ? cvec[idx] : 0.0f;
    float cn = sigf(gf) * cp + sigf(gi) * tanhf(gg);
    cvec[idx] = cn;
    float hv = qg[idx] + sigf(go) * tanhf(cn);
    hout[idx] = hv;
    __nv_bfloat16 h = __float2bfloat16(hv);
    outh[idx] = h;
    outl[idx] = __float2bfloat16(hv - __bfloat162float(h));
}

template <int EPI>
__device__ __forceinline__ void epi_store(int gm, int gn, float v,
                                          float* __restrict__ C, int ldc,
                                          const float* __restrict__ bias,
                                          const float* __restrict__ extra,
                                          __nv_bfloat16* __restrict__ outh,
                                          __nv_bfloat16* __restrict__ outl)
{
    if (EPI == EPI_RELU) {
        float o = fmaxf(v + bias[gn], 0.0f);
        size_t idx = (size_t)gm * ldc + gn;
        __nv_bfloat16 h = __float2bfloat16(o);
        outh[idx] = h;
        outl[idx] = __float2bfloat16(o - __bfloat162float(h));
    } else if (EPI == EPI_RES) {
        C[(size_t)gm * ldc + gn] = v + bias[gn] + extra[(size_t)gm * ldc + gn];
    } else {  // EPI_NB
        float o = tanhf((v + 64.0f * bias[gn]) * extra[gm]);
        size_t idx = (size_t)(gm >> 1) * 256 + (size_t)(gm & 1) * 128 + gn;
        C[idx] = o;
        __nv_bfloat16 h = __float2bfloat16(o);
        outh[idx] = h;
        outl[idx] = __float2bfloat16(o - __bfloat162float(h));
    }
}

template <int EPI, int MI>
__global__ __launch_bounds__(256)
void mma_gemm(const __nv_bfloat16* __restrict__ Ah, const __nv_bfloat16* __restrict__ Al,
              int lda,
              const __nv_bfloat16* __restrict__ Bh, const __nv_bfloat16* __restrict__ Bl,
              int ldb, int K,
              float* __restrict__ C, int ldc,
              const float* __restrict__ bias, const float* __restrict__ extra,
              __nv_bfloat16* __restrict__ outh, __nv_bfloat16* __restrict__ outl,
              float* __restrict__ cvec, float* __restrict__ hout)
{
    constexpr int MT = MI * 32;
    constexpr int ASZ = MT * 128;          // bytes per A stage
    constexpr int STAGE = ASZ + 16384;
    extern __shared__ char smem[];
    const int tid  = threadIdx.x;
    const int wid  = tid >> 5;
    const int lane = tid & 31;
    const int bm = blockIdx.y * MT;
    const int bn = blockIdx.x * 128;
    const int warp_m = wid & 1;
    const int warp_n = wid >> 1;

    float acc[MI][4][4];
    #pragma unroll
    for (int mi = 0; mi < MI; mi++)
        #pragma unroll
        for (int nj = 0; nj < 4; nj++)
            #pragma unroll
            for (int q = 0; q < 4; q++) acc[mi][nj][q] = 0.0f;

    const int a_row_off = (lane & 7) + ((lane >> 3) & 1) * 8;
    const int a_ch_off  = lane >> 4;
    const int b_row_off = lane & 7;
    const int b_ch_off  = (lane >> 3) & 1;

    const int nk = K >> 6;
    const int nt = 3 * nk;

    auto pick = [&](int c, const __nv_bfloat16*& As, const __nv_bfloat16*& Bs, int& koff) {
        int kc = c;
        As = Ah; Bs = Bh;
        if (c >= 2 * nk)  { As = Al; kc = c - 2 * nk; }
        else if (c >= nk) { Bs = Bl; kc = c - nk; }
        koff = kc * 64;
    };

    {
        const __nv_bfloat16 *As, *Bs; int koff;
        pick(0, As, Bs, koff);
        stage_load<MT>(smem, smem + ASZ, As, Bs, lda, ldb, bm, bn, koff, tid);
        asm volatile("cp.async.commit_group;");
    }

    for (int c = 0; c < nt; c++) {
        if (c + 1 < nt) {
            const __nv_bfloat16 *As, *Bs; int koff;
            pick(c + 1, As, Bs, koff);
            char* base = smem + ((c + 1) & 1) * STAGE;
            stage_load<MT>(base, base + ASZ, As, Bs, lda, ldb, bm, bn, koff, tid);
            asm volatile("cp.async.commit_group;");
            asm volatile("cp.async.wait_group 1;");
        } else {
            asm volatile("cp.async.wait_group 0;");
        }
        __syncthreads();

        const uint32_t sa_base = smem_u32(smem + (c & 1) * STAGE);
        const uint32_t sb_base = sa_base + ASZ;

        #pragma unroll
        for (int ks = 0; ks < 4; ks++) {
            uint32_t a[MI][4];
            #pragma unroll
            for (int mi = 0; mi < MI; mi++) {
                uint32_t row = warp_m * (MI * 16) + mi * 16 + a_row_off;
                uint32_t ch  = ks * 2 + a_ch_off;
                uint32_t off = row * 128 + ch * 16;
                uint32_t addr = sa_base + (off ^ ((off >> 3) & 0x70));
                asm volatile("ldmatrix.sync.aligned.m8n8.x4.shared.b16 {%0,%1,%2,%3}, [%4];"
                             : "=r"(a[mi][0]), "=r"(a[mi][1]), "=r"(a[mi][2]), "=r"(a[mi][3])
                             : "r"(addr));
            }
            uint32_t b[4][2];
            #pragma unroll
            for (int nj = 0; nj < 4; nj++) {
                uint32_t row = warp_n * 32 + nj * 8 + b_row_off;
                uint32_t ch  = ks * 2 + b_ch_off;
                uint32_t off = row * 128 + ch * 16;
                uint32_t addr = sb_base + (off ^ ((off >> 3) & 0x70));
                asm volatile("ldmatrix.sync.aligned.m8n8.x2.shared.b16 {%0,%1}, [%2];"
                             : "=r"(b[nj][0]), "=r"(b[nj][1])
                             : "r"(addr));
            }
            #pragma unroll
            for (int mi = 0; mi < MI; mi++)
                #pragma unroll
                for (int nj = 0; nj < 4; nj++)
                    asm volatile(
                        "mma.sync.aligned.m16n8k16.row.col.f32.bf16.bf16.f32 "
                        "{%0,%1,%2,%3}, {%4,%5,%6,%7}, {%8,%9}, {%0,%1,%2,%3};"
                        : "+f"(acc[mi][nj][0]), "+f"(acc[mi][nj][1]),
                          "+f"(acc[mi][nj][2]), "+f"(acc[mi][nj][3])
                        : "r"(a[mi][0]), "r"(a[mi][1]), "r"(a[mi][2]), "r"(a[mi][3]),
                          "r"(b[nj][0]), "r"(b[nj][1]));
        }
        __syncthreads();
    }

    if (EPI == EPI_CELL0 || EPI == EPI_CELL) {
        // packed gate cols: col = u*4 + g. Lane pairs (2k,2k+1) hold (i,f)/(g,o).
        #pragma unroll
        for (int mi = 0; mi < MI; mi++) {
            int m0 = bm + warp_m * (MI * 16) + mi * 16 + (lane >> 2);
            #pragma unroll
            for (int nj = 0; nj < 4; nj++) {
                int n0 = bn + warp_n * 32 + nj * 8 + (lane & 3) * 2;
                float v0 = acc[mi][nj][0], v1 = acc[mi][nj][1];
                float v2 = acc[mi][nj][2], v3 = acc[mi][nj][3];
                if (EPI == EPI_CELL0) {
                    *(float2*)(C + (size_t)m0 * ldc + n0)       = make_float2(v0, v1);
                    *(float2*)(C + (size_t)(m0 + 8) * ldc + n0) = make_float2(v2, v3);
                } else {
                    float2 x0 = *(const float2*)(C + (size_t)m0 * ldc + n0);
                    float2 x1 = *(const float2*)(C + (size_t)(m0 + 8) * ldc + n0);
                    v0 += x0.x; v1 += x0.y; v2 += x1.x; v3 += x1.y;
                }
                float bb0 = bias[n0], bb1 = bias[n0 + 1];
                v0 += bb0; v1 += bb1; v2 += bb0; v3 += bb1;
                float e0 = __shfl_xor_sync(0xFFFFFFFFu, v0, 1);
                float e1 = __shfl_xor_sync(0xFFFFFFFFu, v1, 1);
                float e2 = __shfl_xor_sync(0xFFFFFFFFu, v2, 1);
                float e3 = __shfl_xor_sync(0xFFFFFFFFu, v3, 1);
                if ((lane & 1) == 0) {  // this lane holds (i,f); partner sent (g,o)
                    int u = n0 >> 2;
                    cell_store<EPI>(m0,     u, v0, v1, e0, e1, cvec, extra, hout, outh, outl);
                    cell_store<EPI>(m0 + 8, u, v2, v3, e2, e3, cvec, extra, hout, outh, outl);
                }
            }
        }
    } else {
        #pragma unroll
        for (int mi = 0; mi < MI; mi++) {
            int m0 = bm + warp_m * (MI * 16) + mi * 16 + (lane >> 2);
            #pragma unroll
            for (int nj = 0; nj < 4; nj++) {
                int n0 = bn + warp_n * 32 + nj * 8 + (lane & 3) * 2;
                epi_store<EPI>(m0,     n0,     acc[mi][nj][0], C, ldc, bias, extra, outh, outl);
                epi_store<EPI>(m0,     n0 + 1, acc[mi][nj][1], C, ldc, bias, extra, outh, outl);
                epi_store<EPI>(m0 + 8, n0,     acc[mi][nj][2], C, ldc, bias, extra, outh, outl);
                epi_store<EPI>(m0 + 8, n0 + 1, acc[mi][nj][3], C, ldc, bias, extra, outh, outl);
            }
        }
    }
}

// ================= fused support encoder (one CTA, 512 threads) =============
__global__ __launch_bounds__(512)
void support_fused(const float* __restrict__ BUFS, const float* __restrict__ INVS,
                   const float* __restrict__ gcn_w, const float* __restrict__ gcn_bias,
                   const float* __restrict__ p1w, const float* __restrict__ p1b,
                   const float* __restrict__ p2w, const float* __restrict__ p2b,
                   const float* __restrict__ ln_g, const float* __restrict__ ln_b,
                   float* __restrict__ SG, float* __restrict__ SN)
{
    __shared__ float sB[10][256];
    __shared__ float sInv[10];
    __shared__ float sNB[5][256];
    __shared__ float sH[5][512];
    __shared__ float sZ[5][256];
    __shared__ float sLN[5][256];
    __shared__ float sg[256];
    const int tid = threadIdx.x;
    const int w = tid >> 5, l = tid & 31;

    for (int i = tid; i < 2560; i += 512) sB[i >> 8][i & 255] = BUFS[i];
    if (tid < 10) sInv[tid] = INVS[tid];
    __syncthreads();

    for (int n = w; n < 128; n += 16) {
        float wreg[8];
        #pragma unroll
        for (int kk = 0; kk < 8; kk++) wreg[kk] = gcn_w[n * 256 + kk * 32 + l];
        for (int r = 0; r < 10; r++) {
            float s = 0.f;
            #pragma unroll
            for (int kk = 0; kk < 8; kk++) s += wreg[kk] * sB[r][kk * 32 + l];
            #pragma unroll
            for (int o = 16; o; o >>= 1) s += __shfl_xor_sync(0xFFFFFFFFu, s, o);
            if (l == 0)
                sNB[r >> 1][(r & 1) * 128 + n] = tanhf((s + 64.f * gcn_bias[n]) * sInv[r]);
        }
    }
    __syncthreads();
    for (int n = w; n < 512; n += 16) {
        float wreg[8];
        #pragma unroll
        for (int kk = 0; kk < 8; kk++) wreg[kk] = p1w[n * 256 + kk * 32 + l];
        for (int r = 0; r < 5; r++) {
            float s = 0.f;
            #pragma unroll
            for (int kk = 0; kk < 8; kk++) s += wreg[kk] * sNB[r][kk * 32 + l];
            #pragma unroll
            for (int o = 16; o; o >>= 1) s += __shfl_xor_sync(0xFFFFFFFFu, s, o);
            if (l == 0) sH[r][n] = fmaxf(s + p1b[n], 0.f);
        }
    }
    __syncthreads();
    for (int n = w; n < 256; n += 16) {
        float wreg[16];
        #pragma unroll
        for (int kk = 0; kk < 16; kk++) wreg[kk] = p2w[n * 512 + kk * 32 + l];
        for (int r = 0; r < 5; r++) {
            float s = 0.f;
            #pragma unroll
            for (int kk = 0; kk < 16; kk++) s += wreg[kk] * sH[r][kk * 32 + l];
            #pragma unroll
            for (int o = 16; o; o >>= 1) s += __shfl_xor_sync(0xFFFFFFFFu, s, o);
            if (l == 0) sZ[r][n] = s + p2b[n] + sNB[r][n];
        }
    }
    __syncthreads();
    if (w < 5) {
        float zr[8];
        #pragma unroll
        for (int kk = 0; kk < 8; kk++) zr[kk] = sZ[w][kk * 32 + l];
        float s = 0.f;
        #pragma unroll
        for (int kk = 0; kk < 8; kk++) s += zr[kk];
        #pragma unroll
        for (int o = 16; o; o >>= 1) s += __shfl_xor_sync(0xFFFFFFFFu, s, o);
        float mu = s * (1.f / 256.f);
        float q = 0.f;
        #pragma unroll
        for (int kk = 0; kk < 8; kk++) { float d = zr[kk] - mu; q += d * d; }
        #pragma unroll
        for (int o = 16; o; o >>= 1) q += __shfl_xor_sync(0xFFFFFFFFu, q, o);
        float sig = sqrtf(q * (1.f / 255.f)) + 1e-6f;
        #pragma unroll
        for (int kk = 0; kk < 8; kk++) {
            int ci = kk * 32 + l;
            sLN[w][ci] = ln_g[ci] * (zr[kk] - mu) / sig + ln_b[ci];
        }
    }
    __syncthreads();
    if (tid < 256) {
        float s = 0.f;
        #pragma unroll
        for (int r = 0; r < 5; r++) s += sLN[r][tid];
        float v = s * 0.2f;
        sg[tid] = v;
        SG[tid] = v;
    }
    __syncthreads();
    if (w == 0) {
        float q = 0.f;
        #pragma unroll
        for (int kk = 0; kk < 8; kk++) { float v = sg[kk * 32 + l]; q += v * v; }
        #pragma unroll
        for (int o = 16; o; o >>= 1) q += __shfl_xor_sync(0xFFFFFFFFu, q, o);
        float inv = 1.f / fmaxf(sqrtf(q), 1e-12f);
        #pragma unroll
        for (int kk = 0; kk < 8; kk++) SN[kk * 32 + l] = sg[kk * 32 + l] * inv;
    }
}

// ================= layernorm + bf16 split (query) =================
__global__ void ln_split_kernel(const float* __restrict__ Z,
                                const float* __restrict__ g,
                                const float* __restrict__ bb,
                                float* __restrict__ out,
                                __nv_bfloat16* __restrict__ hi,
                                __nv_bfloat16* __restrict__ lo)
{
    __shared__ float sbuf[256];
    int r = blockIdx.x, t = threadIdx.x;
    float z = Z[(size_t)r * 256 + t];
    float mu = block_sum256(z, sbuf) * (1.0f / 256.0f);
    float d = z - mu;
    float var = block_sum256(d * d, sbuf) * (1.0f / 255.0f);
    float o = g[t] * d / (sqrtf(var) + 1e-6f) + bb[t];
    size_t idx = (size_t)r * 256 + t;
    out[idx] = o;
    __nv_bfloat16 h = __float2bfloat16(o);
    hi[idx] = h;
    lo[idx] = __float2bfloat16(o - __bfloat162float(h));
}

// ================= final cosine similarity =================
__global__ void final_kernel(const float* __restrict__ h,
                             const float* __restrict__ sn,
                             float* __restrict__ out)
{
    __shared__ float sbuf[256];
    int b = blockIdx.x, t = threadIdx.x;
    float v = h[(size_t)b * 256 + t];
    float dot = block_sum256(v * sn[t], sbuf);
    float n2  = block_sum256(v * v, sbuf);
    if (t == 0) out[b] = dot / fmaxf(sqrtf(n2), 1e-12f);
}

// ================= launch =================
extern "C" void kernel_launch(void* const* d_in, const int* in_sizes, int n_in,
                              void* d_out, int out_size)
{
    (void)in_sizes; (void)n_in; (void)out_size;
    const int*   q_l_conn = (const int*)  d_in[2];
    const int*   q_l_deg  = (const int*)  d_in[3];
    const int*   q_r_conn = (const int*)  d_in[4];
    const int*   q_r_deg  = (const int*)  d_in[5];
    const int*   s_l_conn = (const int*)  d_in[6];
    const int*   s_l_deg  = (const int*)  d_in[7];
    const int*   s_r_conn = (const int*)  d_in[8];
    const int*   s_r_deg  = (const int*)  d_in[9];
    const float* emb      = (const float*)d_in[10];
    const float* gcn_w    = (const float*)d_in[11];
    const float* gcn_bias = (const float*)d_in[12];
    const float* proj1_w  = (const float*)d_in[13];
    const float* proj1_b  = (const float*)d_in[14];
    const float* proj2_w  = (const float*)d_in[15];
    const float* proj2_b  = (const float*)d_in[16];
    const float* ln_g     = (const float*)d_in[17];
    const float* ln_b     = (const float*)d_in[18];
    const float* w_ih     = (const float*)d_in[19];
    const float* w_hh     = (const float*)d_in[20];
    const float* b_ih     = (const float*)d_in[21];
    const float* b_hh     = (const float*)d_in[22];
    float* out = (float*)d_out;

    float* S = nullptr;
    cudaGetSymbolAddress((void**)&S, g_scratch);
    __nv_bfloat16* BF = nullptr;
    cudaGetSymbolAddress((void**)&BF, g_bf);

    float* BUFS = S + O_BUFS;  float* INVQ = S + O_INVQ;  float* INVS = S + O_INVS;
    float* QNB  = S + O_QNB;   float* ZQ   = S + O_ZQ;    float* QG   = S + O_QG;
    float* SG   = S + O_SG;    float* SN   = S + O_SN;    float* XW   = S + O_XW;
    float* GB0  = S + O_GB0;   float* GB1  = S + O_GB1;
    float* C    = S + O_C;     float* H    = S + O_H;

    __nv_bfloat16* BQH = BF + B_BUFQH;  __nv_bfloat16* BQL = BF + B_BUFQL;
    __nv_bfloat16* QNBH = BF + B_QNBH;  __nv_bfloat16* QNBL = BF + B_QNBL;
    __nv_bfloat16* HQH = BF + B_HQH;    __nv_bfloat16* HQL = BF + B_HQL;
    __nv_bfloat16* QGH = BF + B_QGH;    __nv_bfloat16* QGL = BF + B_QGL;
    __nv_bfloat16* HH  = BF + B_HH;     __nv_bfloat16* HL  = BF + B_HL;
    __nv_bfloat16* GWH = BF + B_GWH;    __nv_bfloat16* GWL = BF + B_GWL;
    __nv_bfloat16* P1H = BF + B_P1H;    __nv_bfloat16* P1L = BF + B_P1L;
    __nv_bfloat16* P2H = BF + B_P2H;    __nv_bfloat16* P2L = BF + B_P2L;
    __nv_bfloat16* WIHH = BF + B_WIHH;  __nv_bfloat16* WIHL = BF + B_WIHL;
    __nv_bfloat16* WHHH = BF + B_WHHH;  __nv_bfloat16* WHHL = BF + B_WHHL;

    const int SM128 = 2 * (128 * 128 + 16384);  // 65536, MI=4
    const int SM64  = 2 * (64 * 128 + 16384);   // 49152, MI=2
    cudaFuncSetAttribute(mma_gemm<EPI_NB, 2>,    cudaFuncAttributeMaxDynamicSharedMemorySize, SM64);
    cudaFuncSetAttribute(mma_gemm<EPI_RELU, 4>,  cudaFuncAttributeMaxDynamicSharedMemorySize, SM128);
    cudaFuncSetAttribute(mma_gemm<EPI_RES, 2>,   cudaFuncAttributeMaxDynamicSharedMemorySize, SM64);
    cudaFuncSetAttribute(mma_gemm<EPI_CELL0, 4>, cudaFuncAttributeMaxDynamicSharedMemorySize, SM128);
    cudaFuncSetAttribute(mma_gemm<EPI_CELL, 4>,  cudaFuncAttributeMaxDynamicSharedMemorySize, SM128);

    // 1) weight splits + gb0 (one launch), gathers
    split_all_kernel<<<3201, 256>>>(gcn_w, proj1_w, proj2_w, w_ih, w_hh, b_ih, b_hh,
                                    GWH, GWL, P1H, P1L, P2H, P2L,
                                    WIHH, WIHL, WHHH, WHHL, GB0);
    gather_all_kernel<<<8202, 128>>>(q_l_conn, q_l_deg, q_r_conn, q_r_deg,
                                     s_l_conn, s_l_deg, s_r_conn, s_r_deg,
                                     emb, BQH, BQL, INVQ, BUFS, INVS);

    // 2) query GCN (tensor) + fused support encoder + gb1
    mma_gemm<EPI_NB, 2><<<dim3(1, 128), 256, SM64>>>(
        BQH, BQL, 256, GWH, GWL, 256, 256, QNB, 256, gcn_bias, INVQ, QNBH, QNBL,
        nullptr, nullptr);
    support_fused<<<1, 512>>>(BUFS, INVS, gcn_w, gcn_bias, proj1_w, proj1_b,
                              proj2_w, proj2_b, ln_g, ln_b, SG, SN);
    gb1_kernel<<<4, 256>>>(w_hh, SG, GB0, GB1);

    // 3) query MLP on tensor cores + LN
    mma_gemm<EPI_RELU, 4><<<dim3(4, 32), 256, SM128>>>(
        QNBH, QNBL, 256, P1H, P1L, 256, 256, nullptr, 512, proj1_b, nullptr, HQH, HQL,
        nullptr, nullptr);
    mma_gemm<EPI_RES, 2><<<dim3(2, 64), 256, SM64>>>(
        HQH, HQL, 512, P2H, P2L, 512, 512, ZQ, 256, proj2_b, QNB, nullptr, nullptr,
        nullptr, nullptr);
    ln_split_kernel<<<4096, 256>>>(ZQ, ln_g, ln_b, QG, QGH, QGL);

    // 4) LSTM: GEMM + fused cell epilogues (gates interleaved col = u*4+g)
    mma_gemm<EPI_CELL0, 4><<<dim3(8, 32), 256, SM128>>>(
        QGH, QGL, 256, WIHH, WIHL, 256, 256, XW, 1024, GB0, QG, HH, HL, C, H);
    for (int t = 1; t < 4; t++) {
        mma_gemm<EPI_CELL, 4><<<dim3(8, 32), 256, SM128>>>(
            HH, HL, 256, WHHH, WHHL, 256, 256, XW, 1024, GB1, QG, HH, HL, C, H);
    }

    // 5) cosine similarity
    final_kernel<<<4096, 256>>>(H, SN, out);
}

// round 9
// speedup vs baseline: 1.2340x; 1.2340x over previous
#include <cuda_runtime.h>
#include <cuda_bf16.h>
#include <math.h>
#include <stdint.h>

// ---------------------------------------------------------------------------
// EmbedMatcher on GB300 (sm_103 plain PTX -> mma.sync bf16x3 tensor cores).
//  - Support rows batched through the query GEMM pipeline (rows 8192..8201 /
//    4096..4100) -- no serial 1-CTA support encoder.
//  - Gate-interleaved packing (col = unit*4+gate): LSTM cell fused into GEMM
//    epilogue via lane-pair shfl. Dead-gate elimination (N 2048->1024).
//  - rank-1 support factorization (recurrent K 512->256 + gb1 bias).
// ---------------------------------------------------------------------------

__device__ __forceinline__ uint32_t smem_u32(const void* p) {
    uint32_t a;
    asm("{ .reg .u64 t; cvta.to.shared.u64 t, %1; cvt.u32.u64 %0, t; }"
        : "=r"(a) : "l"(p));
    return a;
}

// ================= fp32 scratch =================
constexpr size_t N_INVQ = 8320;
constexpr size_t N_QNB  = 4224UL * 256;
constexpr size_t N_ZQ   = 4224UL * 256;
constexpr size_t N_QG   = 4224UL * 256;
constexpr size_t N_SG   = 256;
constexpr size_t N_SN   = 256;
constexpr size_t N_XW   = 4096UL * 1024;
constexpr size_t N_GB0  = 1024;
constexpr size_t N_GB1  = 1024;
constexpr size_t N_C    = 4096UL * 256;
constexpr size_t N_H    = 4096UL * 256;

constexpr size_t O_INVQ = 0;
constexpr size_t O_QNB  = O_INVQ + N_INVQ;
constexpr size_t O_ZQ   = O_QNB  + N_QNB;
constexpr size_t O_QG   = O_ZQ   + N_ZQ;
constexpr size_t O_SG   = O_QG   + N_QG;
constexpr size_t O_SN   = O_SG   + N_SG;
constexpr size_t O_XW   = O_SN   + N_SN;
constexpr size_t O_GB0  = O_XW   + N_XW;
constexpr size_t O_GB1  = O_GB0  + N_GB0;
constexpr size_t O_C    = O_GB1  + N_GB1;
constexpr size_t O_H    = O_C    + N_C;
constexpr size_t SCRATCH_TOTAL = O_H + N_H;
__device__ float g_scratch[SCRATCH_TOTAL];

// ================= bf16 split scratch =================
constexpr size_t B_BUFQH = 0;
constexpr size_t B_BUFQL = B_BUFQH + 8320UL * 256;
constexpr size_t B_QNBH  = B_BUFQL + 8320UL * 256;
constexpr size_t B_QNBL  = B_QNBH  + 4224UL * 256;
constexpr size_t B_HQH   = B_QNBL  + 4224UL * 256;
constexpr size_t B_HQL   = B_HQH   + 4224UL * 512;
constexpr size_t B_QGH   = B_HQL   + 4224UL * 512;
constexpr size_t B_QGL   = B_QGH   + 4224UL * 256;
constexpr size_t B_HH    = B_QGL   + 4224UL * 256;
constexpr size_t B_HL    = B_HH    + 4096UL * 256;
constexpr size_t B_GWH   = B_HL    + 4096UL * 256;
constexpr size_t B_GWL   = B_GWH   + 128UL * 256;
constexpr size_t B_P1H   = B_GWL   + 128UL * 256;
constexpr size_t B_P1L   = B_P1H   + 512UL * 256;
constexpr size_t B_P2H   = B_P1L   + 512UL * 256;
constexpr size_t B_P2L   = B_P2H   + 256UL * 512;
constexpr size_t B_WIHH  = B_P2L   + 256UL * 512;
constexpr size_t B_WIHL  = B_WIHH  + 1024UL * 256;
constexpr size_t B_WHHH  = B_WIHL  + 1024UL * 256;
constexpr size_t B_WHHL  = B_WHHH  + 1024UL * 256;
constexpr size_t BF_TOTAL = B_WHHL + 1024UL * 256;
__device__ __align__(128) __nv_bfloat16 g_bf[BF_TOTAL];

// ================= helpers =================
__device__ __forceinline__ float sigf(float x) { return 1.0f / (1.0f + expf(-x)); }

__device__ __forceinline__ float block_sum256(float v, float* sbuf) {
    int t = threadIdx.x;
    sbuf[t] = v;
    __syncthreads();
    #pragma unroll
    for (int s = 128; s > 0; s >>= 1) {
        if (t < s) sbuf[t] += sbuf[t + s];
        __syncthreads();
    }
    float r = sbuf[0];
    __syncthreads();
    return r;
}

// ================= fused gather (query + support), float4 loads ==============
__global__ void gather_all_kernel(const int* __restrict__ qlc, const int* __restrict__ qld,
                                  const int* __restrict__ qrc, const int* __restrict__ qrd,
                                  const int* __restrict__ slc, const int* __restrict__ sld,
                                  const int* __restrict__ src_, const int* __restrict__ srd,
                                  const float* __restrict__ emb,
                                  __nv_bfloat16* __restrict__ bqh, __nv_bfloat16* __restrict__ bql,
                                  float* __restrict__ invq)
{
    __shared__ int sc[128];
    __shared__ float4 red[2][4][32];
    int b = blockIdx.x;
    const int* conn; const int* deg; int r, row;
    if (b < 4096)      { r = b;        conn = qlc;  deg = qld; row = 2 * r; }
    else if (b < 8192) { r = b - 4096; conn = qrc;  deg = qrd; row = 2 * r + 1; }
    else if (b < 8197) { r = b - 8192; conn = slc;  deg = sld; row = 8192 + 2 * r; }
    else               { r = b - 8197; conn = src_; deg = srd; row = 8192 + 2 * r + 1; }
    int t = threadIdx.x;  // 128
    int w = t >> 5, l = t & 31;
    sc[t] = conn[r * 128 + t];
    __syncthreads();
    float4 a0 = make_float4(0.f, 0.f, 0.f, 0.f);
    float4 a1 = make_float4(0.f, 0.f, 0.f, 0.f);
    #pragma unroll 4
    for (int i = 0; i < 16; i++) {
        int n = w * 16 + i;
        float4 v0 = __ldg((const float4*)(emb + (size_t)sc[2 * n]     * 128) + l);
        float4 v1 = __ldg((const float4*)(emb + (size_t)sc[2 * n + 1] * 128) + l);
        a0.x += v0.x; a0.y += v0.y; a0.z += v0.z; a0.w += v0.w;
        a1.x += v1.x; a1.y += v1.y; a1.z += v1.z; a1.w += v1.w;
    }
    red[0][w][l] = a0;
    red[1][w][l] = a1;
    __syncthreads();
    if (t < 64) {
        int which = t >> 5, ll = t & 31;
        float4 p0 = red[which][0][ll], p1 = red[which][1][ll];
        float4 p2 = red[which][2][ll], p3 = red[which][3][ll];
        float s[4];
        s[0] = p0.x + p1.x + p2.x + p3.x;
        s[1] = p0.y + p1.y + p2.y + p3.y;
        s[2] = p0.z + p1.z + p2.z + p3.z;
        s[3] = p0.w + p1.w + p2.w + p3.w;
        size_t base = (size_t)row * 256 + which * 128 + ll * 4;
        #pragma unroll
        for (int j = 0; j < 4; j++) {
            __nv_bfloat16 h = __float2bfloat16(s[j]);
            bqh[base + j] = h;
            bql[base + j] = __float2bfloat16(s[j] - __bfloat162float(h));
        }
    }
    if (t == 0) invq[row] = 1.0f / (float)max(deg[r], 1);
}

// ================= merged weight splits + gb0 ================================
__global__ void split_all_kernel(const float* __restrict__ gcn_w,
                                 const float* __restrict__ p1w,
                                 const float* __restrict__ p2w,
                                 const float* __restrict__ w_ih,
                                 const float* __restrict__ w_hh,
                                 const float* __restrict__ b_ih,
                                 const float* __restrict__ b_hh,
                                 __nv_bfloat16* __restrict__ gwh, __nv_bfloat16* __restrict__ gwl,
                                 __nv_bfloat16* __restrict__ p1h, __nv_bfloat16* __restrict__ p1l,
                                 __nv_bfloat16* __restrict__ p2h, __nv_bfloat16* __restrict__ p2l,
                                 __nv_bfloat16* __restrict__ wih, __nv_bfloat16* __restrict__ wil,
                                 __nv_bfloat16* __restrict__ whh, __nv_bfloat16* __restrict__ whl,
                                 float* __restrict__ gb0)
{
    int b = blockIdx.x, t = threadIdx.x;
    if (b == 3200) {
        #pragma unroll
        for (int k = 0; k < 4; k++) {
            int col = k * 256 + t;
            int g = col & 3, u = col >> 2;
            gb0[col] = b_ih[g * 512 + u] + b_hh[g * 512 + u];
        }
        return;
    }
    float v;
    __nv_bfloat16 *hi, *lo;
    int idx;
    if (b < 128)       { idx = b * 256 + t;          v = gcn_w[idx]; hi = gwh; lo = gwl; }
    else if (b < 640)  { idx = (b - 128) * 256 + t;  v = p1w[idx];   hi = p1h; lo = p1l; }
    else if (b < 1152) { idx = (b - 640) * 256 + t;  v = p2w[idx];   hi = p2h; lo = p2l; }
    else {
        const float* W; int ldw;
        if (b < 2176) { idx = (b - 1152) * 256 + t; W = w_ih; ldw = 256; hi = wih; lo = wil; }
        else          { idx = (b - 2176) * 256 + t; W = w_hh; ldw = 512; hi = whh; lo = whl; }
        int orow = idx >> 8, c = idx & 255;
        int u = orow >> 2, g = orow & 3;           // packed col = u*4+g
        v = W[(size_t)(g * 512 + u) * ldw + c];
    }
    __nv_bfloat16 h = __float2bfloat16(v);
    hi[idx] = h;
    lo[idx] = __float2bfloat16(v - __bfloat162float(h));
}

// ================= gb1 = gb0 + rvec (packed) =================
__global__ void gb1_kernel(const float* __restrict__ w_hh,
                           const float* __restrict__ sg,
                           const float* __restrict__ gb0,
                           float* __restrict__ gb1)
{
    int col = blockIdx.x * 256 + threadIdx.x;  // 1024
    int g = col & 3, u = col >> 2;
    const float* w = w_hh + (size_t)(g * 512 + u) * 512 + 256;
    float s = 0.0f;
    #pragma unroll 8
    for (int k = 0; k < 256; k++) s += w[k] * sg[k];
    gb1[col] = gb0[col] + s;
}

// ================= unified mma.sync bf16x3 GEMM ==============================
enum { EPI_RELU = 1, EPI_RES = 2, EPI_NB = 3, EPI_CELL0 = 4, EPI_CELL = 5 };

__device__ __forceinline__ void cp16(uint32_t daddr, const void* g) {
    asm volatile("cp.async.cg.shared.global [%0], [%1], 16;" :: "r"(daddr), "l"(g));
}

template <int MT>
__device__ __forceinline__ void stage_load(char* sa, char* sb,
                                           const __nv_bfloat16* __restrict__ Asrc,
                                           const __nv_bfloat16* __restrict__ Bsrc,
                                           int lda, int ldb, int bm, int bn,
                                           int koff, int tid)
{
    #pragma unroll
    for (int i = 0; i < MT / 32; i++) {
        int idx = i * 256 + tid;
        int row = idx >> 3, ch = idx & 7;
        uint32_t off = (uint32_t)(row * 128 + ch * 16);
        uint32_t sw  = off ^ ((off >> 3) & 0x70);
        cp16(smem_u32(sa + sw), Asrc + (size_t)(bm + row) * lda + koff + ch * 8);
    }
    #pragma unroll
    for (int i = 0; i < 4; i++) {
        int idx = i * 256 + tid;
        int row = idx >> 3, ch = idx & 7;
        uint32_t off = (uint32_t)(row * 128 + ch * 16);
        uint32_t sw  = off ^ ((off >> 3) & 0x70);
        cp16(smem_u32(sb + sw), Bsrc + (size_t)(bn + row) * ldb + koff + ch * 8);
    }
}

template <int EPI>
__device__ __forceinline__ void cell_store(int r, int u,
                                           float gi, float gf, float gg, float go,
                                           float* __restrict__ cvec,
                                           const float* __restrict__ qg,
                                           float* __restrict__ hout,
                                           __nv_bfloat16* __restrict__ outh,
                                           __nv_bfloat16* __restrict__ outl)
{
    size_t idx = (size_t)r * 256 + u;
    float cp = (EPI == EPI_CELL) ? cvec[idx] : 0.0f;
    float cn = sigf(gf) * cp + sigf(gi) * tanhf(gg);
    cvec[idx] = cn;
    float hv = qg[idx] + sigf(go) * tanhf(cn);
    hout[idx] = hv;
    __nv_bfloat16 h = __float2bfloat16(hv);
    outh[idx] = h;
    outl[idx] = __float2bfloat16(hv - __bfloat162float(h));
}

template <int EPI>
__device__ __forceinline__ void epi_store(int gm, int gn, float v,
                                          float* __restrict__ C, int ldc,
                                          const float* __restrict__ bias,
                                          const float* __restrict__ extra,
                                          __nv_bfloat16* __restrict__ outh,
                                          __nv_bfloat16* __restrict__ outl)
{
    if (EPI == EPI_RELU) {
        float o = fmaxf(v + bias[gn], 0.0f);
        size_t idx = (size_t)gm * ldc + gn;
        __nv_bfloat16 h = __float2bfloat16(o);
        outh[idx] = h;
        outl[idx] = __float2bfloat16(o - __bfloat162float(h));
    } else if (EPI == EPI_RES) {
        C[(size_t)gm * ldc + gn] = v + bias[gn] + extra[(size_t)gm * ldc + gn];
    } else {  // EPI_NB
        float o = tanhf((v + 64.0f * bias[gn]) * extra[gm]);
        size_t idx = (size_t)(gm >> 1) * 256 + (size_t)(gm & 1) * 128 + gn;
        C[idx] = o;
        __nv_bfloat16 h = __float2bfloat16(o);
        outh[idx] = h;
        outl[idx] = __float2bfloat16(o - __bfloat162float(h));
    }
}

template <int EPI, int MI>
__global__ __launch_bounds__(256)
void mma_gemm(const __nv_bfloat16* __restrict__ Ah, const __nv_bfloat16* __restrict__ Al,
              int lda,
              const __nv_bfloat16* __restrict__ Bh, const __nv_bfloat16* __restrict__ Bl,
              int ldb, int K,
              float* __restrict__ C, int ldc,
              const float* __restrict__ bias, const float* __restrict__ extra,
              __nv_bfloat16* __restrict__ outh, __nv_bfloat16* __restrict__ outl,
              float* __restrict__ cvec, float* __restrict__ hout)
{
    constexpr int MT = MI * 32;
    constexpr int ASZ = MT * 128;
    constexpr int STAGE = ASZ + 16384;
    extern __shared__ char smem[];
    const int tid  = threadIdx.x;
    const int wid  = tid >> 5;
    const int lane = tid & 31;
    const int bm = blockIdx.y * MT;
    const int bn = blockIdx.x * 128;
    const int warp_m = wid & 1;
    const int warp_n = wid >> 1;

    float acc[MI][4][4];
    #pragma unroll
    for (int mi = 0; mi < MI; mi++)
        #pragma unroll
        for (int nj = 0; nj < 4; nj++)
            #pragma unroll
            for (int q = 0; q < 4; q++) acc[mi][nj][q] = 0.0f;

    const int a_row_off = (lane & 7) + ((lane >> 3) & 1) * 8;
    const int a_ch_off  = lane >> 4;
    const int b_row_off = lane & 7;
    const int b_ch_off  = (lane >> 3) & 1;

    const int nk = K >> 6;
    const int nt = 3 * nk;

    auto pick = [&](int c, const __nv_bfloat16*& As, const __nv_bfloat16*& Bs, int& koff) {
        int kc = c;
        As = Ah; Bs = Bh;
        if (c >= 2 * nk)  { As = Al; kc = c - 2 * nk; }
        else if (c >= nk) { Bs = Bl; kc = c - nk; }
        koff = kc * 64;
    };

    {
        const __nv_bfloat16 *As, *Bs; int koff;
        pick(0, As, Bs, koff);
        stage_load<MT>(smem, smem + ASZ, As, Bs, lda, ldb, bm, bn, koff, tid);
        asm volatile("cp.async.commit_group;");
    }

    for (int c = 0; c < nt; c++) {
        if (c + 1 < nt) {
            const __nv_bfloat16 *As, *Bs; int koff;
            pick(c + 1, As, Bs, koff);
            char* base = smem + ((c + 1) & 1) * STAGE;
            stage_load<MT>(base, base + ASZ, As, Bs, lda, ldb, bm, bn, koff, tid);
            asm volatile("cp.async.commit_group;");
            asm volatile("cp.async.wait_group 1;");
        } else {
            asm volatile("cp.async.wait_group 0;");
        }
        __syncthreads();

        const uint32_t sa_base = smem_u32(smem + (c & 1) * STAGE);
        const uint32_t sb_base = sa_base + ASZ;

        #pragma unroll
        for (int ks = 0; ks < 4; ks++) {
            uint32_t a[MI][4];
            #pragma unroll
            for (int mi = 0; mi < MI; mi++) {
                uint32_t row = warp_m * (MI * 16) + mi * 16 + a_row_off;
                uint32_t ch  = ks * 2 + a_ch_off;
                uint32_t off = row * 128 + ch * 16;
                uint32_t addr = sa_base + (off ^ ((off >> 3) & 0x70));
                asm volatile("ldmatrix.sync.aligned.m8n8.x4.shared.b16 {%0,%1,%2,%3}, [%4];"
                             : "=r"(a[mi][0]), "=r"(a[mi][1]), "=r"(a[mi][2]), "=r"(a[mi][3])
                             : "r"(addr));
            }
            uint32_t b[4][2];
            #pragma unroll
            for (int nj = 0; nj < 4; nj++) {
                uint32_t row = warp_n * 32 + nj * 8 + b_row_off;
                uint32_t ch  = ks * 2 + b_ch_off;
                uint32_t off = row * 128 + ch * 16;
                uint32_t addr = sb_base + (off ^ ((off >> 3) & 0x70));
                asm volatile("ldmatrix.sync.aligned.m8n8.x2.shared.b16 {%0,%1}, [%2];"
                             : "=r"(b[nj][0]), "=r"(b[nj][1])
                             : "r"(addr));
            }
            #pragma unroll
            for (int mi = 0; mi < MI; mi++)
                #pragma unroll
                for (int nj = 0; nj < 4; nj++)
                    asm volatile(
                        "mma.sync.aligned.m16n8k16.row.col.f32.bf16.bf16.f32 "
                        "{%0,%1,%2,%3}, {%4,%5,%6,%7}, {%8,%9}, {%0,%1,%2,%3};"
                        : "+f"(acc[mi][nj][0]), "+f"(acc[mi][nj][1]),
                          "+f"(acc[mi][nj][2]), "+f"(acc[mi][nj][3])
                        : "r"(a[mi][0]), "r"(a[mi][1]), "r"(a[mi][2]), "r"(a[mi][3]),
                          "r"(b[nj][0]), "r"(b[nj][1]));
        }
        __syncthreads();
    }

    if (EPI == EPI_CELL0 || EPI == EPI_CELL) {
        #pragma unroll
        for (int mi = 0; mi < MI; mi++) {
            int m0 = bm + warp_m * (MI * 16) + mi * 16 + (lane >> 2);
            #pragma unroll
            for (int nj = 0; nj < 4; nj++) {
                int n0 = bn + warp_n * 32 + nj * 8 + (lane & 3) * 2;
                float v0 = acc[mi][nj][0], v1 = acc[mi][nj][1];
                float v2 = acc[mi][nj][2], v3 = acc[mi][nj][3];
                if (EPI == EPI_CELL0) {
                    *(float2*)(C + (size_t)m0 * ldc + n0)       = make_float2(v0, v1);
                    *(float2*)(C + (size_t)(m0 + 8) * ldc + n0) = make_float2(v2, v3);
                } else {
                    float2 x0 = *(const float2*)(C + (size_t)m0 * ldc + n0);
                    float2 x1 = *(const float2*)(C + (size_t)(m0 + 8) * ldc + n0);
                    v0 += x0.x; v1 += x0.y; v2 += x1.x; v3 += x1.y;
                }
                float bb0 = bias[n0], bb1 = bias[n0 + 1];
                v0 += bb0; v1 += bb1; v2 += bb0; v3 += bb1;
                float e0 = __shfl_xor_sync(0xFFFFFFFFu, v0, 1);
                float e1 = __shfl_xor_sync(0xFFFFFFFFu, v1, 1);
                float e2 = __shfl_xor_sync(0xFFFFFFFFu, v2, 1);
                float e3 = __shfl_xor_sync(0xFFFFFFFFu, v3, 1);
                if ((lane & 1) == 0) {
                    int u = n0 >> 2;
                    cell_store<EPI>(m0,     u, v0, v1, e0, e1, cvec, extra, hout, outh, outl);
                    cell_store<EPI>(m0 + 8, u, v2, v3, e2, e3, cvec, extra, hout, outh, outl);
                }
            }
        }
    } else {
        #pragma unroll
        for (int mi = 0; mi < MI; mi++) {
            int m0 = bm + warp_m * (MI * 16) + mi * 16 + (lane >> 2);
            #pragma unroll
            for (int nj = 0; nj < 4; nj++) {
                int n0 = bn + warp_n * 32 + nj * 8 + (lane & 3) * 2;
                epi_store<EPI>(m0,     n0,     acc[mi][nj][0], C, ldc, bias, extra, outh, outl);
                epi_store<EPI>(m0,     n0 + 1, acc[mi][nj][1], C, ldc, bias, extra, outh, outl);
                epi_store<EPI>(m0 + 8, n0,     acc[mi][nj][2], C, ldc, bias, extra, outh, outl);
                epi_store<EPI>(m0 + 8, n0 + 1, acc[mi][nj][3], C, ldc, bias, extra, outh, outl);
            }
        }
    }
}

// ================= layernorm + bf16 split =================
__global__ void ln_split_kernel(const float* __restrict__ Z,
                                const float* __restrict__ g,
                                const float* __restrict__ bb,
                                float* __restrict__ out,
                                __nv_bfloat16* __restrict__ hi,
                                __nv_bfloat16* __restrict__ lo)
{
    __shared__ float sbuf[256];
    int r = blockIdx.x, t = threadIdx.x;
    float z = Z[(size_t)r * 256 + t];
    float mu = block_sum256(z, sbuf) * (1.0f / 256.0f);
    float d = z - mu;
    float var = block_sum256(d * d, sbuf) * (1.0f / 255.0f);
    float o = g[t] * d / (sqrtf(var) + 1e-6f) + bb[t];
    size_t idx = (size_t)r * 256 + t;
    out[idx] = o;
    __nv_bfloat16 h = __float2bfloat16(o);
    hi[idx] = h;
    lo[idx] = __float2bfloat16(o - __bfloat162float(h));
}

// ================= SG (mean of LN rows 4096..4100) + SN =================
__global__ void sg_sn_kernel(const float* __restrict__ QG,
                             float* __restrict__ SG, float* __restrict__ SN)
{
    __shared__ float sbuf[256];
    int t = threadIdx.x;
    float s = 0.f;
    #pragma unroll
    for (int r = 0; r < 5; r++) s += QG[(size_t)(4096 + r) * 256 + t];
    float v = s * 0.2f;
    SG[t] = v;
    float n2 = block_sum256(v * v, sbuf);
    SN[t] = v / fmaxf(sqrtf(n2), 1e-12f);
}

// ================= final cosine similarity =================
__global__ void final_kernel(const float* __restrict__ h,
                             const float* __restrict__ sn,
                             float* __restrict__ out)
{
    __shared__ float sbuf[256];
    int b = blockIdx.x, t = threadIdx.x;
    float v = h[(size_t)b * 256 + t];
    float dot = block_sum256(v * sn[t], sbuf);
    float n2  = block_sum256(v * v, sbuf);
    if (t == 0) out[b] = dot / fmaxf(sqrtf(n2), 1e-12f);
}

// ================= launch =================
extern "C" void kernel_launch(void* const* d_in, const int* in_sizes, int n_in,
                              void* d_out, int out_size)
{
    (void)in_sizes; (void)n_in; (void)out_size;
    const int*   q_l_conn = (const int*)  d_in[2];
    const int*   q_l_deg  = (const int*)  d_in[3];
    const int*   q_r_conn = (const int*)  d_in[4];
    const int*   q_r_deg  = (const int*)  d_in[5];
    const int*   s_l_conn = (const int*)  d_in[6];
    const int*   s_l_deg  = (const int*)  d_in[7];
    const int*   s_r_conn = (const int*)  d_in[8];
    const int*   s_r_deg  = (const int*)  d_in[9];
    const float* emb      = (const float*)d_in[10];
    const float* gcn_w    = (const float*)d_in[11];
    const float* gcn_bias = (const float*)d_in[12];
    const float* proj1_w  = (const float*)d_in[13];
    const float* proj1_b  = (const float*)d_in[14];
    const float* proj2_w  = (const float*)d_in[15];
    const float* proj2_b  = (const float*)d_in[16];
    const float* ln_g     = (const float*)d_in[17];
    const float* ln_b     = (const float*)d_in[18];
    const float* w_ih     = (const float*)d_in[19];
    const float* w_hh     = (const float*)d_in[20];
    const float* b_ih     = (const float*)d_in[21];
    const float* b_hh     = (const float*)d_in[22];
    float* out = (float*)d_out;

    float* S = nullptr;
    cudaGetSymbolAddress((void**)&S, g_scratch);
    __nv_bfloat16* BF = nullptr;
    cudaGetSymbolAddress((void**)&BF, g_bf);

    float* INVQ = S + O_INVQ;  float* QNB  = S + O_QNB;   float* ZQ = S + O_ZQ;
    float* QG   = S + O_QG;    float* SG   = S + O_SG;    float* SN = S + O_SN;
    float* XW   = S + O_XW;    float* GB0  = S + O_GB0;   float* GB1 = S + O_GB1;
    float* C    = S + O_C;     float* H    = S + O_H;

    __nv_bfloat16* BQH = BF + B_BUFQH;  __nv_bfloat16* BQL = BF + B_BUFQL;
    __nv_bfloat16* QNBH = BF + B_QNBH;  __nv_bfloat16* QNBL = BF + B_QNBL;
    __nv_bfloat16* HQH = BF + B_HQH;    __nv_bfloat16* HQL = BF + B_HQL;
    __nv_bfloat16* QGH = BF + B_QGH;    __nv_bfloat16* QGL = BF + B_QGL;
    __nv_bfloat16* HH  = BF + B_HH;     __nv_bfloat16* HL  = BF + B_HL;
    __nv_bfloat16* GWH = BF + B_GWH;    __nv_bfloat16* GWL = BF + B_GWL;
    __nv_bfloat16* P1H = BF + B_P1H;    __nv_bfloat16* P1L = BF + B_P1L;
    __nv_bfloat16* P2H = BF + B_P2H;    __nv_bfloat16* P2L = BF + B_P2L;
    __nv_bfloat16* WIHH = BF + B_WIHH;  __nv_bfloat16* WIHL = BF + B_WIHL;
    __nv_bfloat16* WHHH = BF + B_WHHH;  __nv_bfloat16* WHHL = BF + B_WHHL;

    const int SM128 = 2 * (128 * 128 + 16384);  // 65536, MI=4
    const int SM64  = 2 * (64 * 128 + 16384);   // 49152, MI=2
    cudaFuncSetAttribute(mma_gemm<EPI_NB, 2>,    cudaFuncAttributeMaxDynamicSharedMemorySize, SM64);
    cudaFuncSetAttribute(mma_gemm<EPI_RELU, 4>,  cudaFuncAttributeMaxDynamicSharedMemorySize, SM128);
    cudaFuncSetAttribute(mma_gemm<EPI_RES, 4>,   cudaFuncAttributeMaxDynamicSharedMemorySize, SM128);
    cudaFuncSetAttribute(mma_gemm<EPI_CELL0, 4>, cudaFuncAttributeMaxDynamicSharedMemorySize, SM128);
    cudaFuncSetAttribute(mma_gemm<EPI_CELL, 4>,  cudaFuncAttributeMaxDynamicSharedMemorySize, SM128);

    // 1) weight splits + gb0, gathers (query + support -> rows 8192..8201)
    split_all_kernel<<<3201, 256>>>(gcn_w, proj1_w, proj2_w, w_ih, w_hh, b_ih, b_hh,
                                    GWH, GWL, P1H, P1L, P2H, P2L,
                                    WIHH, WIHL, WHHH, WHHL, GB0);
    gather_all_kernel<<<8202, 128>>>(q_l_conn, q_l_deg, q_r_conn, q_r_deg,
                                     s_l_conn, s_l_deg, s_r_conn, s_r_deg,
                                     emb, BQH, BQL, INVQ);

    // 2) GCN over 8202 rows (129 tiles of 64) -> QNB rows 0..4100 (+pad)
    mma_gemm<EPI_NB, 2><<<dim3(1, 129), 256, SM64>>>(
        BQH, BQL, 256, GWH, GWL, 256, 256, QNB, 256, gcn_bias, INVQ, QNBH, QNBL,
        nullptr, nullptr);

    // 3) MLP over 4224 rows (33 tiles of 128) + LN over 4101 rows
    mma_gemm<EPI_RELU, 4><<<dim3(4, 33), 256, SM128>>>(
        QNBH, QNBL, 256, P1H, P1L, 256, 256, nullptr, 512, proj1_b, nullptr, HQH, HQL,
        nullptr, nullptr);
    mma_gemm<EPI_RES, 4><<<dim3(2, 33), 256, SM128>>>(
        HQH, HQL, 512, P2H, P2L, 512, 512, ZQ, 256, proj2_b, QNB, nullptr, nullptr,
        nullptr, nullptr);
    ln_split_kernel<<<4101, 256>>>(ZQ, ln_g, ln_b, QG, QGH, QGL);

    // 4) support vector + gb1
    sg_sn_kernel<<<1, 256>>>(QG, SG, SN);
    gb1_kernel<<<4, 256>>>(w_hh, SG, GB0, GB1);

    // 5) LSTM: GEMM + fused cell epilogues
    mma_gemm<EPI_CELL0, 4><<<dim3(8, 32), 256, SM128>>>(
        QGH, QGL, 256, WIHH, WIHL, 256, 256, XW, 1024, GB0, QG, HH, HL, C, H);
    for (int t = 1; t < 4; t++) {
        mma_gemm<EPI_CELL, 4><<<dim3(8, 32), 256, SM128>>>(
            HH, HL, 256, WHHH, WHHL, 256, 256, XW, 1024, GB1, QG, HH, HL, C, H);
    }

    // 6) cosine similarity
    final_kernel<<<4096, 256>>>(H, SN, out);
}

// round 10
// speedup vs baseline: 1.4422x; 1.1687x over previous
#include <cuda_runtime.h>
#include <cuda_bf16.h>
#include <math.h>
#include <stdint.h>

// ---------------------------------------------------------------------------
// EmbedMatcher on GB300 (sm_103 plain PTX -> mma.sync bf16x3 tensor cores).
//  - All big GEMMs: 64x128 CTA tiles (MI=2), 2 CTAs/SM (launch_bounds(256,2)),
//    3-stage cp.async pipeline, ONE syncthreads per K-chunk.
//  - Support rows batched through the query GEMM pipeline (rows 4096..4100).
//  - Gate-interleaved packing: LSTM cell fused into GEMM epilogue.
//  - Dead-gate elimination (N 2048->1024) + rank-1 support factorization.
// ---------------------------------------------------------------------------

__device__ __forceinline__ uint32_t smem_u32(const void* p) {
    uint32_t a;
    asm("{ .reg .u64 t; cvta.to.shared.u64 t, %1; cvt.u32.u64 %0, t; }"
        : "=r"(a) : "l"(p));
    return a;
}

// ================= fp32 scratch =================
constexpr size_t N_INVQ = 8320;
constexpr size_t N_QNB  = 4224UL * 256;
constexpr size_t N_ZQ   = 4224UL * 256;
constexpr size_t N_QG   = 4224UL * 256;
constexpr size_t N_SG   = 256;
constexpr size_t N_SN   = 256;
constexpr size_t N_XW   = 4096UL * 1024;
constexpr size_t N_GB0  = 1024;
constexpr size_t N_GB1  = 1024;
constexpr size_t N_C    = 4096UL * 256;
constexpr size_t N_H    = 4096UL * 256;

constexpr size_t O_INVQ = 0;
constexpr size_t O_QNB  = O_INVQ + N_INVQ;
constexpr size_t O_ZQ   = O_QNB  + N_QNB;
constexpr size_t O_QG   = O_ZQ   + N_ZQ;
constexpr size_t O_SG   = O_QG   + N_QG;
constexpr size_t O_SN   = O_SG   + N_SG;
constexpr size_t O_XW   = O_SN   + N_SN;
constexpr size_t O_GB0  = O_XW   + N_XW;
constexpr size_t O_GB1  = O_GB0  + N_GB0;
constexpr size_t O_C    = O_GB1  + N_GB1;
constexpr size_t O_H    = O_C    + N_C;
constexpr size_t SCRATCH_TOTAL = O_H + N_H;
__device__ float g_scratch[SCRATCH_TOTAL];

// ================= bf16 split scratch =================
constexpr size_t B_BUFQH = 0;
constexpr size_t B_BUFQL = B_BUFQH + 8320UL * 256;
constexpr size_t B_QNBH  = B_BUFQL + 8320UL * 256;
constexpr size_t B_QNBL  = B_QNBH  + 4224UL * 256;
constexpr size_t B_HQH   = B_QNBL  + 4224UL * 256;
constexpr size_t B_HQL   = B_HQH   + 4224UL * 512;
constexpr size_t B_QGH   = B_HQL   + 4224UL * 512;
constexpr size_t B_QGL   = B_QGH   + 4224UL * 256;
constexpr size_t B_HH    = B_QGL   + 4224UL * 256;
constexpr size_t B_HL    = B_HH    + 4096UL * 256;
constexpr size_t B_GWH   = B_HL    + 4096UL * 256;
constexpr size_t B_GWL   = B_GWH   + 128UL * 256;
constexpr size_t B_P1H   = B_GWL   + 128UL * 256;
constexpr size_t B_P1L   = B_P1H   + 512UL * 256;
constexpr size_t B_P2H   = B_P1L   + 512UL * 256;
constexpr size_t B_P2L   = B_P2H   + 256UL * 512;
constexpr size_t B_WIHH  = B_P2L   + 256UL * 512;
constexpr size_t B_WIHL  = B_WIHH  + 1024UL * 256;
constexpr size_t B_WHHH  = B_WIHL  + 1024UL * 256;
constexpr size_t B_WHHL  = B_WHHH  + 1024UL * 256;
constexpr size_t BF_TOTAL = B_WHHL + 1024UL * 256;
__device__ __align__(128) __nv_bfloat16 g_bf[BF_TOTAL];

// ================= helpers =================
__device__ __forceinline__ float sigf(float x) { return 1.0f / (1.0f + expf(-x)); }

__device__ __forceinline__ float block_sum256(float v, float* sbuf) {
    int t = threadIdx.x;
    sbuf[t] = v;
    __syncthreads();
    #pragma unroll
    for (int s = 128; s > 0; s >>= 1) {
        if (t < s) sbuf[t] += sbuf[t + s];
        __syncthreads();
    }
    float r = sbuf[0];
    __syncthreads();
    return r;
}

// ================= fused gather (query + support), float4 loads ==============
__global__ void gather_all_kernel(const int* __restrict__ qlc, const int* __restrict__ qld,
                                  const int* __restrict__ qrc, const int* __restrict__ qrd,
                                  const int* __restrict__ slc, const int* __restrict__ sld,
                                  const int* __restrict__ src_, const int* __restrict__ srd,
                                  const float* __restrict__ emb,
                                  __nv_bfloat16* __restrict__ bqh, __nv_bfloat16* __restrict__ bql,
                                  float* __restrict__ invq)
{
    __shared__ int sc[128];
    __shared__ float4 red[2][4][32];
    int b = blockIdx.x;
    const int* conn; const int* deg; int r, row;
    if (b < 4096)      { r = b;        conn = qlc;  deg = qld; row = 2 * r; }
    else if (b < 8192) { r = b - 4096; conn = qrc;  deg = qrd; row = 2 * r + 1; }
    else if (b < 8197) { r = b - 8192; conn = slc;  deg = sld; row = 8192 + 2 * r; }
    else               { r = b - 8197; conn = src_; deg = srd; row = 8192 + 2 * r + 1; }
    int t = threadIdx.x;  // 128
    int w = t >> 5, l = t & 31;
    sc[t] = conn[r * 128 + t];
    __syncthreads();
    float4 a0 = make_float4(0.f, 0.f, 0.f, 0.f);
    float4 a1 = make_float4(0.f, 0.f, 0.f, 0.f);
    #pragma unroll 4
    for (int i = 0; i < 16; i++) {
        int n = w * 16 + i;
        float4 v0 = __ldg((const float4*)(emb + (size_t)sc[2 * n]     * 128) + l);
        float4 v1 = __ldg((const float4*)(emb + (size_t)sc[2 * n + 1] * 128) + l);
        a0.x += v0.x; a0.y += v0.y; a0.z += v0.z; a0.w += v0.w;
        a1.x += v1.x; a1.y += v1.y; a1.z += v1.z; a1.w += v1.w;
    }
    red[0][w][l] = a0;
    red[1][w][l] = a1;
    __syncthreads();
    if (t < 64) {
        int which = t >> 5, ll = t & 31;
        float4 p0 = red[which][0][ll], p1 = red[which][1][ll];
        float4 p2 = red[which][2][ll], p3 = red[which][3][ll];
        float s[4];
        s[0] = p0.x + p1.x + p2.x + p3.x;
        s[1] = p0.y + p1.y + p2.y + p3.y;
        s[2] = p0.z + p1.z + p2.z + p3.z;
        s[3] = p0.w + p1.w + p2.w + p3.w;
        size_t base = (size_t)row * 256 + which * 128 + ll * 4;
        #pragma unroll
        for (int j = 0; j < 4; j++) {
            __nv_bfloat16 h = __float2bfloat16(s[j]);
            bqh[base + j] = h;
            bql[base + j] = __float2bfloat16(s[j] - __bfloat162float(h));
        }
    }
    if (t == 0) invq[row] = 1.0f / (float)max(deg[r], 1);
}

// ================= merged weight splits + gb0 ================================
__global__ void split_all_kernel(const float* __restrict__ gcn_w,
                                 const float* __restrict__ p1w,
                                 const float* __restrict__ p2w,
                                 const float* __restrict__ w_ih,
                                 const float* __restrict__ w_hh,
                                 const float* __restrict__ b_ih,
                                 const float* __restrict__ b_hh,
                                 __nv_bfloat16* __restrict__ gwh, __nv_bfloat16* __restrict__ gwl,
                                 __nv_bfloat16* __restrict__ p1h, __nv_bfloat16* __restrict__ p1l,
                                 __nv_bfloat16* __restrict__ p2h, __nv_bfloat16* __restrict__ p2l,
                                 __nv_bfloat16* __restrict__ wih, __nv_bfloat16* __restrict__ wil,
                                 __nv_bfloat16* __restrict__ whh, __nv_bfloat16* __restrict__ whl,
                                 float* __restrict__ gb0)
{
    int b = blockIdx.x, t = threadIdx.x;
    if (b == 3200) {
        #pragma unroll
        for (int k = 0; k < 4; k++) {
            int col = k * 256 + t;
            int g = col & 3, u = col >> 2;
            gb0[col] = b_ih[g * 512 + u] + b_hh[g * 512 + u];
        }
        return;
    }
    float v;
    __nv_bfloat16 *hi, *lo;
    int idx;
    if (b < 128)       { idx = b * 256 + t;          v = gcn_w[idx]; hi = gwh; lo = gwl; }
    else if (b < 640)  { idx = (b - 128) * 256 + t;  v = p1w[idx];   hi = p1h; lo = p1l; }
    else if (b < 1152) { idx = (b - 640) * 256 + t;  v = p2w[idx];   hi = p2h; lo = p2l; }
    else {
        const float* W; int ldw;
        if (b < 2176) { idx = (b - 1152) * 256 + t; W = w_ih; ldw = 256; hi = wih; lo = wil; }
        else          { idx = (b - 2176) * 256 + t; W = w_hh; ldw = 512; hi = whh; lo = whl; }
        int orow = idx >> 8, c = idx & 255;
        int u = orow >> 2, g = orow & 3;           // packed col = u*4+g
        v = W[(size_t)(g * 512 + u) * ldw + c];
    }
    __nv_bfloat16 h = __float2bfloat16(v);
    hi[idx] = h;
    lo[idx] = __float2bfloat16(v - __bfloat162float(h));
}

// ================= gb1 = gb0 + rvec (packed) =================
__global__ void gb1_kernel(const float* __restrict__ w_hh,
                           const float* __restrict__ sg,
                           const float* __restrict__ gb0,
                           float* __restrict__ gb1)
{
    int col = blockIdx.x * 256 + threadIdx.x;  // 1024
    int g = col & 3, u = col >> 2;
    const float* w = w_hh + (size_t)(g * 512 + u) * 512 + 256;
    float s = 0.0f;
    #pragma unroll 8
    for (int k = 0; k < 256; k++) s += w[k] * sg[k];
    gb1[col] = gb0[col] + s;
}

// ================= unified mma.sync bf16x3 GEMM ==============================
// 64x128 CTA tile (MI=2), 8 warps (2m x 4n), warp tile 32x32, K-chunks of 64,
// 3-stage cp.async pipeline, one __syncthreads per chunk, 2 CTAs/SM.
enum { EPI_RELU = 1, EPI_RES = 2, EPI_NB = 3, EPI_CELL0 = 4, EPI_CELL = 5 };

__device__ __forceinline__ void cp16(uint32_t daddr, const void* g) {
    asm volatile("cp.async.cg.shared.global [%0], [%1], 16;" :: "r"(daddr), "l"(g));
}

template <int MT>
__device__ __forceinline__ void stage_load(char* sa, char* sb,
                                           const __nv_bfloat16* __restrict__ Asrc,
                                           const __nv_bfloat16* __restrict__ Bsrc,
                                           int lda, int ldb, int bm, int bn,
                                           int koff, int tid)
{
    #pragma unroll
    for (int i = 0; i < MT / 32; i++) {
        int idx = i * 256 + tid;
        int row = idx >> 3, ch = idx & 7;
        uint32_t off = (uint32_t)(row * 128 + ch * 16);
        uint32_t sw  = off ^ ((off >> 3) & 0x70);
        cp16(smem_u32(sa + sw), Asrc + (size_t)(bm + row) * lda + koff + ch * 8);
    }
    #pragma unroll
    for (int i = 0; i < 4; i++) {
        int idx = i * 256 + tid;
        int row = idx >> 3, ch = idx & 7;
        uint32_t off = (uint32_t)(row * 128 + ch * 16);
        uint32_t sw  = off ^ ((off >> 3) & 0x70);
        cp16(smem_u32(sb + sw), Bsrc + (size_t)(bn + row) * ldb + koff + ch * 8);
    }
}

template <int EPI>
__device__ __forceinline__ void cell_store(int r, int u,
                                           float gi, float gf, float gg, float go,
                                           float* __restrict__ cvec,
                                           const float* __restrict__ qg,
                                           float* __restrict__ hout,
                                           __nv_bfloat16* __restrict__ outh,
                                           __nv_bfloat16* __restrict__ outl)
{
    size_t idx = (size_t)r * 256 + u;
    float cp = (EPI == EPI_CELL) ? cvec[idx] : 0.0f;
    float cn = sigf(gf) * cp + sigf(gi) * tanhf(gg);
    cvec[idx] = cn;
    float hv = qg[idx] + sigf(go) * tanhf(cn);
    hout[idx] = hv;
    __nv_bfloat16 h = __float2bfloat16(hv);
    outh[idx] = h;
    outl[idx] = __float2bfloat16(hv - __bfloat162float(h));
}

template <int EPI>
__device__ __forceinline__ void epi_store(int gm, int gn, float v,
                                          float* __restrict__ C, int ldc,
                                          const float* __restrict__ bias,
                                          const float* __restrict__ extra,
                                          __nv_bfloat16* __restrict__ outh,
                                          __nv_bfloat16* __restrict__ outl)
{
    if (EPI == EPI_RELU) {
        float o = fmaxf(v + bias[gn], 0.0f);
        size_t idx = (size_t)gm * ldc + gn;
        __nv_bfloat16 h = __float2bfloat16(o);
        outh[idx] = h;
        outl[idx] = __float2bfloat16(o - __bfloat162float(h));
    } else if (EPI == EPI_RES) {
        C[(size_t)gm * ldc + gn] = v + bias[gn] + extra[(size_t)gm * ldc + gn];
    } else {  // EPI_NB
        float o = tanhf((v + 64.0f * bias[gn]) * extra[gm]);
        size_t idx = (size_t)(gm >> 1) * 256 + (size_t)(gm & 1) * 128 + gn;
        C[idx] = o;
        __nv_bfloat16 h = __float2bfloat16(o);
        outh[idx] = h;
        outl[idx] = __float2bfloat16(o - __bfloat162float(h));
    }
}

template <int EPI>
__global__ __launch_bounds__(256, 2)
void mma_gemm(const __nv_bfloat16* __restrict__ Ah, const __nv_bfloat16* __restrict__ Al,
              int lda,
              const __nv_bfloat16* __restrict__ Bh, const __nv_bfloat16* __restrict__ Bl,
              int ldb, int K,
              float* __restrict__ C, int ldc,
              const float* __restrict__ bias, const float* __restrict__ extra,
              __nv_bfloat16* __restrict__ outh, __nv_bfloat16* __restrict__ outl,
              float* __restrict__ cvec, float* __restrict__ hout)
{
    constexpr int MI = 2;
    constexpr int MT = 64;
    constexpr int ASZ = MT * 128;          // 8 KB
    constexpr int STAGE = ASZ + 16384;     // 24 KB
    extern __shared__ char smem[];         // 3 stages = 72 KB
    const int tid  = threadIdx.x;
    const int wid  = tid >> 5;
    const int lane = tid & 31;
    const int bm = blockIdx.y * MT;
    const int bn = blockIdx.x * 128;
    const int warp_m = wid & 1;
    const int warp_n = wid >> 1;

    float acc[MI][4][4];
    #pragma unroll
    for (int mi = 0; mi < MI; mi++)
        #pragma unroll
        for (int nj = 0; nj < 4; nj++)
            #pragma unroll
            for (int q = 0; q < 4; q++) acc[mi][nj][q] = 0.0f;

    const int a_row_off = (lane & 7) + ((lane >> 3) & 1) * 8;
    const int a_ch_off  = lane >> 4;
    const int b_row_off = lane & 7;
    const int b_ch_off  = (lane >> 3) & 1;

    const int nk = K >> 6;
    const int nt = 3 * nk;

    auto pick = [&](int c, const __nv_bfloat16*& As, const __nv_bfloat16*& Bs, int& koff) {
        int kc = c;
        As = Ah; Bs = Bh;
        if (c >= 2 * nk)  { As = Al; kc = c - 2 * nk; }
        else if (c >= nk) { Bs = Bl; kc = c - nk; }
        koff = kc * 64;
    };

    // prologue: stages 0 and 1
    {
        const __nv_bfloat16 *As, *Bs; int koff;
        pick(0, As, Bs, koff);
        stage_load<MT>(smem, smem + ASZ, As, Bs, lda, ldb, bm, bn, koff, tid);
        asm volatile("cp.async.commit_group;");
        pick(1, As, Bs, koff);
        stage_load<MT>(smem + STAGE, smem + STAGE + ASZ, As, Bs, lda, ldb, bm, bn, koff, tid);
        asm volatile("cp.async.commit_group;");
    }

    int buf = 0;
    for (int c = 0; c < nt; c++) {
        if (c + 1 < nt) asm volatile("cp.async.wait_group 1;");
        else            asm volatile("cp.async.wait_group 0;");
        __syncthreads();

        const uint32_t sa_base = smem_u32(smem + buf * STAGE);
        const uint32_t sb_base = sa_base + ASZ;

        #pragma unroll
        for (int ks = 0; ks < 4; ks++) {
            uint32_t a[MI][4];
            #pragma unroll
            for (int mi = 0; mi < MI; mi++) {
                uint32_t row = warp_m * (MI * 16) + mi * 16 + a_row_off;
                uint32_t ch  = ks * 2 + a_ch_off;
                uint32_t off = row * 128 + ch * 16;
                uint32_t addr = sa_base + (off ^ ((off >> 3) & 0x70));
                asm volatile("ldmatrix.sync.aligned.m8n8.x4.shared.b16 {%0,%1,%2,%3}, [%4];"
                             : "=r"(a[mi][0]), "=r"(a[mi][1]), "=r"(a[mi][2]), "=r"(a[mi][3])
                             : "r"(addr));
            }
            uint32_t b[4][2];
            #pragma unroll
            for (int nj = 0; nj < 4; nj++) {
                uint32_t row = warp_n * 32 + nj * 8 + b_row_off;
                uint32_t ch  = ks * 2 + b_ch_off;
                uint32_t off = row * 128 + ch * 16;
                uint32_t addr = sb_base + (off ^ ((off >> 3) & 0x70));
                asm volatile("ldmatrix.sync.aligned.m8n8.x2.shared.b16 {%0,%1}, [%2];"
                             : "=r"(b[nj][0]), "=r"(b[nj][1])
                             : "r"(addr));
            }
            #pragma unroll
            for (int mi = 0; mi < MI; mi++)
                #pragma unroll
                for (int nj = 0; nj < 4; nj++)
                    asm volatile(
                        "mma.sync.aligned.m16n8k16.row.col.f32.bf16.bf16.f32 "
                        "{%0,%1,%2,%3}, {%4,%5,%6,%7}, {%8,%9}, {%0,%1,%2,%3};"
                        : "+f"(acc[mi][nj][0]), "+f"(acc[mi][nj][1]),
                          "+f"(acc[mi][nj][2]), "+f"(acc[mi][nj][3])
                        : "r"(a[mi][0]), "r"(a[mi][1]), "r"(a[mi][2]), "r"(a[mi][3]),
                          "r"(b[nj][0]), "r"(b[nj][1]));
        }

        // prefetch chunk c+2 into the buffer freed by chunk c-1
        if (c + 2 < nt) {
            const __nv_bfloat16 *As, *Bs; int koff;
            pick(c + 2, As, Bs, koff);
            int nb = (buf + 2) % 3;
            char* base = smem + nb * STAGE;
            stage_load<MT>(base, base + ASZ, As, Bs, lda, ldb, bm, bn, koff, tid);
            asm volatile("cp.async.commit_group;");
        }
        buf = (buf + 1) % 3;
    }

    if (EPI == EPI_CELL0 || EPI == EPI_CELL) {
        #pragma unroll
        for (int mi = 0; mi < MI; mi++) {
            int m0 = bm + warp_m * (MI * 16) + mi * 16 + (lane >> 2);
            #pragma unroll
            for (int nj = 0; nj < 4; nj++) {
                int n0 = bn + warp_n * 32 + nj * 8 + (lane & 3) * 2;
                float v0 = acc[mi][nj][0], v1 = acc[mi][nj][1];
                float v2 = acc[mi][nj][2], v3 = acc[mi][nj][3];
                if (EPI == EPI_CELL0) {
                    *(float2*)(C + (size_t)m0 * ldc + n0)       = make_float2(v0, v1);
                    *(float2*)(C + (size_t)(m0 + 8) * ldc + n0) = make_float2(v2, v3);
                } else {
                    float2 x0 = *(const float2*)(C + (size_t)m0 * ldc + n0);
                    float2 x1 = *(const float2*)(C + (size_t)(m0 + 8) * ldc + n0);
                    v0 += x0.x; v1 += x0.y; v2 += x1.x; v3 += x1.y;
                }
                float bb0 = bias[n0], bb1 = bias[n0 + 1];
                v0 += bb0; v1 += bb1; v2 += bb0; v3 += bb1;
                float e0 = __shfl_xor_sync(0xFFFFFFFFu, v0, 1);
                float e1 = __shfl_xor_sync(0xFFFFFFFFu, v1, 1);
                float e2 = __shfl_xor_sync(0xFFFFFFFFu, v2, 1);
                float e3 = __shfl_xor_sync(0xFFFFFFFFu, v3, 1);
                if ((lane & 1) == 0) {
                    int u = n0 >> 2;
                    cell_store<EPI>(m0,     u, v0, v1, e0, e1, cvec, extra, hout, outh, outl);
                    cell_store<EPI>(m0 + 8, u, v2, v3, e2, e3, cvec, extra, hout, outh, outl);
                }
            }
        }
    } else {
        #pragma unroll
        for (int mi = 0; mi < MI; mi++) {
            int m0 = bm + warp_m * (MI * 16) + mi * 16 + (lane >> 2);
            #pragma unroll
            for (int nj = 0; nj < 4; nj++) {
                int n0 = bn + warp_n * 32 + nj * 8 + (lane & 3) * 2;
                epi_store<EPI>(m0,     n0,     acc[mi][nj][0], C, ldc, bias, extra, outh, outl);
                epi_store<EPI>(m0,     n0 + 1, acc[mi][nj][1], C, ldc, bias, extra, outh, outl);
                epi_store<EPI>(m0 + 8, n0,     acc[mi][nj][2], C, ldc, bias, extra, outh, outl);
                epi_store<EPI>(m0 + 8, n0 + 1, acc[mi][nj][3], C, ldc, bias, extra, outh, outl);
            }
        }
    }
}

// ================= layernorm + bf16 split =================
__global__ void ln_split_kernel(const float* __restrict__ Z,
                                const float* __restrict__ g,
                                const float* __restrict__ bb,
                                float* __restrict__ out,
                                __nv_bfloat16* __restrict__ hi,
                                __nv_bfloat16* __restrict__ lo)
{
    __shared__ float sbuf[256];
    int r = blockIdx.x, t = threadIdx.x;
    float z = Z[(size_t)r * 256 + t];
    float mu = block_sum256(z, sbuf) * (1.0f / 256.0f);
    float d = z - mu;
    float var = block_sum256(d * d, sbuf) * (1.0f / 255.0f);
    float o = g[t] * d / (sqrtf(var) + 1e-6f) + bb[t];
    size_t idx = (size_t)r * 256 + t;
    out[idx] = o;
    __nv_bfloat16 h = __float2bfloat16(o);
    hi[idx] = h;
    lo[idx] = __float2bfloat16(o - __bfloat162float(h));
}

// ================= SG (mean of LN rows 4096..4100) + SN =================
__global__ void sg_sn_kernel(const float* __restrict__ QG,
                             float* __restrict__ SG, float* __restrict__ SN)
{
    __shared__ float sbuf[256];
    int t = threadIdx.x;
    float s = 0.f;
    #pragma unroll
    for (int r = 0; r < 5; r++) s += QG[(size_t)(4096 + r) * 256 + t];
    float v = s * 0.2f;
    SG[t] = v;
    float n2 = block_sum256(v * v, sbuf);
    SN[t] = v / fmaxf(sqrtf(n2), 1e-12f);
}

// ================= final cosine similarity =================
__global__ void final_kernel(const float* __restrict__ h,
                             const float* __restrict__ sn,
                             float* __restrict__ out)
{
    __shared__ float sbuf[256];
    int b = blockIdx.x, t = threadIdx.x;
    float v = h[(size_t)b * 256 + t];
    float dot = block_sum256(v * sn[t], sbuf);
    float n2  = block_sum256(v * v, sbuf);
    if (t == 0) out[b] = dot / fmaxf(sqrtf(n2), 1e-12f);
}

// ================= launch =================
extern "C" void kernel_launch(void* const* d_in, const int* in_sizes, int n_in,
                              void* d_out, int out_size)
{
    (void)in_sizes; (void)n_in; (void)out_size;
    const int*   q_l_conn = (const int*)  d_in[2];
    const int*   q_l_deg  = (const int*)  d_in[3];
    const int*   q_r_conn = (const int*)  d_in[4];
    const int*   q_r_deg  = (const int*)  d_in[5];
    const int*   s_l_conn = (const int*)  d_in[6];
    const int*   s_l_deg  = (const int*)  d_in[7];
    const int*   s_r_conn = (const int*)  d_in[8];
    const int*   s_r_deg  = (const int*)  d_in[9];
    const float* emb      = (const float*)d_in[10];
    const float* gcn_w    = (const float*)d_in[11];
    const float* gcn_bias = (const float*)d_in[12];
    const float* proj1_w  = (const float*)d_in[13];
    const float* proj1_b  = (const float*)d_in[14];
    const float* proj2_w  = (const float*)d_in[15];
    const float* proj2_b  = (const float*)d_in[16];
    const float* ln_g     = (const float*)d_in[17];
    const float* ln_b     = (const float*)d_in[18];
    const float* w_ih     = (const float*)d_in[19];
    const float* w_hh     = (const float*)d_in[20];
    const float* b_ih     = (const float*)d_in[21];
    const float* b_hh     = (const float*)d_in[22];
    float* out = (float*)d_out;

    float* S = nullptr;
    cudaGetSymbolAddress((void**)&S, g_scratch);
    __nv_bfloat16* BF = nullptr;
    cudaGetSymbolAddress((void**)&BF, g_bf);

    float* INVQ = S + O_INVQ;  float* QNB  = S + O_QNB;   float* ZQ = S + O_ZQ;
    float* QG   = S + O_QG;    float* SG   = S + O_SG;    float* SN = S + O_SN;
    float* XW   = S + O_XW;    float* GB0  = S + O_GB0;   float* GB1 = S + O_GB1;
    float* C    = S + O_C;     float* H    = S + O_H;

    __nv_bfloat16* BQH = BF + B_BUFQH;  __nv_bfloat16* BQL = BF + B_BUFQL;
    __nv_bfloat16* QNBH = BF + B_QNBH;  __nv_bfloat16* QNBL = BF + B_QNBL;
    __nv_bfloat16* HQH = BF + B_HQH;    __nv_bfloat16* HQL = BF + B_HQL;
    __nv_bfloat16* QGH = BF + B_QGH;    __nv_bfloat16* QGL = BF + B_QGL;
    __nv_bfloat16* HH  = BF + B_HH;     __nv_bfloat16* HL  = BF + B_HL;
    __nv_bfloat16* GWH = BF + B_GWH;    __nv_bfloat16* GWL = BF + B_GWL;
    __nv_bfloat16* P1H = BF + B_P1H;    __nv_bfloat16* P1L = BF + B_P1L;
    __nv_bfloat16* P2H = BF + B_P2H;    __nv_bfloat16* P2L = BF + B_P2L;
    __nv_bfloat16* WIHH = BF + B_WIHH;  __nv_bfloat16* WIHL = BF + B_WIHL;
    __nv_bfloat16* WHHH = BF + B_WHHH;  __nv_bfloat16* WHHL = BF + B_WHHL;

    const int SM3 = 3 * (64 * 128 + 16384);  // 73728
    cudaFuncSetAttribute(mma_gemm<EPI_NB>,    cudaFuncAttributeMaxDynamicSharedMemorySize, SM3);
    cudaFuncSetAttribute(mma_gemm<EPI_RELU>,  cudaFuncAttributeMaxDynamicSharedMemorySize, SM3);
    cudaFuncSetAttribute(mma_gemm<EPI_RES>,   cudaFuncAttributeMaxDynamicSharedMemorySize, SM3);
    cudaFuncSetAttribute(mma_gemm<EPI_CELL0>, cudaFuncAttributeMaxDynamicSharedMemorySize, SM3);
    cudaFuncSetAttribute(mma_gemm<EPI_CELL>,  cudaFuncAttributeMaxDynamicSharedMemorySize, SM3);

    // 1) weight splits + gb0, gathers (query + support -> rows 8192..8201)
    split_all_kernel<<<3201, 256>>>(gcn_w, proj1_w, proj2_w, w_ih, w_hh, b_ih, b_hh,
                                    GWH, GWL, P1H, P1L, P2H, P2L,
                                    WIHH, WIHL, WHHH, WHHL, GB0);
    gather_all_kernel<<<8202, 128>>>(q_l_conn, q_l_deg, q_r_conn, q_r_deg,
                                     s_l_conn, s_l_deg, s_r_conn, s_r_deg,
                                     emb, BQH, BQL, INVQ);

    // 2) GCN over 8202 rows (129 tiles of 64) -> QNB rows 0..4100 (+pad)
    mma_gemm<EPI_NB><<<dim3(1, 129), 256, SM3>>>(
        BQH, BQL, 256, GWH, GWL, 256, 256, QNB, 256, gcn_bias, INVQ, QNBH, QNBL,
        nullptr, nullptr);

    // 3) MLP over 4224 rows (66 tiles of 64) + LN over 4101 rows
    mma_gemm<EPI_RELU><<<dim3(4, 66), 256, SM3>>>(
        QNBH, QNBL, 256, P1H, P1L, 256, 256, nullptr, 512, proj1_b, nullptr, HQH, HQL,
        nullptr, nullptr);
    mma_gemm<EPI_RES><<<dim3(2, 66), 256, SM3>>>(
        HQH, HQL, 512, P2H, P2L, 512, 512, ZQ, 256, proj2_b, QNB, nullptr, nullptr,
        nullptr, nullptr);
    ln_split_kernel<<<4101, 256>>>(ZQ, ln_g, ln_b, QG, QGH, QGL);

    // 4) support vector + gb1
    sg_sn_kernel<<<1, 256>>>(QG, SG, SN);
    gb1_kernel<<<4, 256>>>(w_hh, SG, GB0, GB1);

    // 5) LSTM: GEMM + fused cell epilogues (64-row tiles -> 512 CTAs)
    mma_gemm<EPI_CELL0><<<dim3(8, 64), 256, SM3>>>(
        QGH, QGL, 256, WIHH, WIHL, 256, 256, XW, 1024, GB0, QG, HH, HL, C, H);
    for (int t = 1; t < 4; t++) {
        mma_gemm<EPI_CELL><<<dim3(8, 64), 256, SM3>>>(
            HH, HL, 256, WHHH, WHHL, 256, 256, XW, 1024, GB1, QG, HH, HL, C, H);
    }

    // 6) cosine similarity
    final_kernel<<<4096, 256>>>(H, SN, out);
}

// round 11
// speedup vs baseline: 1.4587x; 1.0114x over previous
#include <cuda_runtime.h>
#include <cuda_bf16.h>
#include <math.h>
#include <stdint.h>

// ---------------------------------------------------------------------------
// EmbedMatcher on GB300 (sm_103 plain PTX -> mma.sync bf16x3 tensor cores).
//  - 64x128 CTA tiles, 2 CTAs/SM, 3-stage cp.async, 1 sync/chunk.
//  - Split-K=2 on the underfilled GEMMs (NB, RES); partial sums folded into
//    the consumers (nb_combine / ln_split).
//  - B fragments loaded with ldmatrix.x4 (4 LDSM / 8 HMMA per k-step).
//  - LSTM cell fused in GEMM epilogue; dead-gate elim; rank-1 support.
// ---------------------------------------------------------------------------

__device__ __forceinline__ uint32_t smem_u32(const void* p) {
    uint32_t a;
    asm("{ .reg .u64 t; cvta.to.shared.u64 t, %1; cvt.u32.u64 %0, t; }"
        : "=r"(a) : "l"(p));
    return a;
}

// ================= fp32 scratch =================
constexpr size_t PSTRIDE_NB  = 8320UL * 128;   // NB partial stride
constexpr size_t PSTRIDE_RES = 4224UL * 256;   // RES partial stride

constexpr size_t N_INVQ = 8320;
constexpr size_t N_QNBP = 2 * PSTRIDE_NB;
constexpr size_t N_QNB  = 4224UL * 256;
constexpr size_t N_ZP   = 2 * PSTRIDE_RES;
constexpr size_t N_QG   = 4224UL * 256;
constexpr size_t N_SG   = 256;
constexpr size_t N_SN   = 256;
constexpr size_t N_XW   = 4096UL * 1024;
constexpr size_t N_GB0  = 1024;
constexpr size_t N_GB1  = 1024;
constexpr size_t N_C    = 4096UL * 256;
constexpr size_t N_H    = 4096UL * 256;

constexpr size_t O_INVQ = 0;
constexpr size_t O_QNBP = O_INVQ + N_INVQ;
constexpr size_t O_QNB  = O_QNBP + N_QNBP;
constexpr size_t O_ZP   = O_QNB  + N_QNB;
constexpr size_t O_QG   = O_ZP   + N_ZP;
constexpr size_t O_SG   = O_QG   + N_QG;
constexpr size_t O_SN   = O_SG   + N_SG;
constexpr size_t O_XW   = O_SN   + N_SN;
constexpr size_t O_GB0  = O_XW   + N_XW;
constexpr size_t O_GB1  = O_GB0  + N_GB0;
constexpr size_t O_C    = O_GB1  + N_GB1;
constexpr size_t O_H    = O_C    + N_C;
constexpr size_t SCRATCH_TOTAL = O_H + N_H;
__device__ float g_scratch[SCRATCH_TOTAL];

// ================= bf16 split scratch =================
constexpr size_t B_BUFQH = 0;
constexpr size_t B_BUFQL = B_BUFQH + 8320UL * 256;
constexpr size_t B_QNBH  = B_BUFQL + 8320UL * 256;
constexpr size_t B_QNBL  = B_QNBH  + 4224UL * 256;
constexpr size_t B_HQH   = B_QNBL  + 4224UL * 256;
constexpr size_t B_HQL   = B_HQH   + 4224UL * 512;
constexpr size_t B_QGH   = B_HQL   + 4224UL * 512;
constexpr size_t B_QGL   = B_QGH   + 4224UL * 256;
constexpr size_t B_HH    = B_QGL   + 4224UL * 256;
constexpr size_t B_HL    = B_HH    + 4096UL * 256;
constexpr size_t B_GWH   = B_HL    + 4096UL * 256;
constexpr size_t B_GWL   = B_GWH   + 128UL * 256;
constexpr size_t B_P1H   = B_GWL   + 128UL * 256;
constexpr size_t B_P1L   = B_P1H   + 512UL * 256;
constexpr size_t B_P2H   = B_P1L   + 512UL * 256;
constexpr size_t B_P2L   = B_P2H   + 256UL * 512;
constexpr size_t B_WIHH  = B_P2L   + 256UL * 512;
constexpr size_t B_WIHL  = B_WIHH  + 1024UL * 256;
constexpr size_t B_WHHH  = B_WIHL  + 1024UL * 256;
constexpr size_t B_WHHL  = B_WHHH  + 1024UL * 256;
constexpr size_t BF_TOTAL = B_WHHL + 1024UL * 256;
__device__ __align__(128) __nv_bfloat16 g_bf[BF_TOTAL];

// ================= helpers =================
__device__ __forceinline__ float sigf(float x) { return 1.0f / (1.0f + expf(-x)); }

__device__ __forceinline__ float block_sum256(float v, float* sbuf) {
    int t = threadIdx.x;
    sbuf[t] = v;
    __syncthreads();
    #pragma unroll
    for (int s = 128; s > 0; s >>= 1) {
        if (t < s) sbuf[t] += sbuf[t + s];
        __syncthreads();
    }
    float r = sbuf[0];
    __syncthreads();
    return r;
}

// ================= fused gather (query + support), float4 loads ==============
__global__ void gather_all_kernel(const int* __restrict__ qlc, const int* __restrict__ qld,
                                  const int* __restrict__ qrc, const int* __restrict__ qrd,
                                  const int* __restrict__ slc, const int* __restrict__ sld,
                                  const int* __restrict__ src_, const int* __restrict__ srd,
                                  const float* __restrict__ emb,
                                  __nv_bfloat16* __restrict__ bqh, __nv_bfloat16* __restrict__ bql,
                                  float* __restrict__ invq)
{
    __shared__ int sc[128];
    __shared__ float4 red[2][4][32];
    int b = blockIdx.x;
    const int* conn; const int* deg; int r, row;
    if (b < 4096)      { r = b;        conn = qlc;  deg = qld; row = 2 * r; }
    else if (b < 8192) { r = b - 4096; conn = qrc;  deg = qrd; row = 2 * r + 1; }
    else if (b < 8197) { r = b - 8192; conn = slc;  deg = sld; row = 8192 + 2 * r; }
    else               { r = b - 8197; conn = src_; deg = srd; row = 8192 + 2 * r + 1; }
    int t = threadIdx.x;  // 128
    int w = t >> 5, l = t & 31;
    sc[t] = conn[r * 128 + t];
    __syncthreads();
    float4 a0 = make_float4(0.f, 0.f, 0.f, 0.f);
    float4 a1 = make_float4(0.f, 0.f, 0.f, 0.f);
    #pragma unroll 4
    for (int i = 0; i < 16; i++) {
        int n = w * 16 + i;
        float4 v0 = __ldg((const float4*)(emb + (size_t)sc[2 * n]     * 128) + l);
        float4 v1 = __ldg((const float4*)(emb + (size_t)sc[2 * n + 1] * 128) + l);
        a0.x += v0.x; a0.y += v0.y; a0.z += v0.z; a0.w += v0.w;
        a1.x += v1.x; a1.y += v1.y; a1.z += v1.z; a1.w += v1.w;
    }
    red[0][w][l] = a0;
    red[1][w][l] = a1;
    __syncthreads();
    if (t < 64) {
        int which = t >> 5, ll = t & 31;
        float4 p0 = red[which][0][ll], p1 = red[which][1][ll];
        float4 p2 = red[which][2][ll], p3 = red[which][3][ll];
        float s[4];
        s[0] = p0.x + p1.x + p2.x + p3.x;
        s[1] = p0.y + p1.y + p2.y + p3.y;
        s[2] = p0.z + p1.z + p2.z + p3.z;
        s[3] = p0.w + p1.w + p2.w + p3.w;
        size_t base = (size_t)row * 256 + which * 128 + ll * 4;
        #pragma unroll
        for (int j = 0; j < 4; j++) {
            __nv_bfloat16 h = __float2bfloat16(s[j]);
            bqh[base + j] = h;
            bql[base + j] = __float2bfloat16(s[j] - __bfloat162float(h));
        }
    }
    if (t == 0) invq[row] = 1.0f / (float)max(deg[r], 1);
}

// ================= merged weight splits + gb0 ================================
__global__ void split_all_kernel(const float* __restrict__ gcn_w,
                                 const float* __restrict__ p1w,
                                 const float* __restrict__ p2w,
                                 const float* __restrict__ w_ih,
                                 const float* __restrict__ w_hh,
                                 const float* __restrict__ b_ih,
                                 const float* __restrict__ b_hh,
                                 __nv_bfloat16* __restrict__ gwh, __nv_bfloat16* __restrict__ gwl,
                                 __nv_bfloat16* __restrict__ p1h, __nv_bfloat16* __restrict__ p1l,
                                 __nv_bfloat16* __restrict__ p2h, __nv_bfloat16* __restrict__ p2l,
                                 __nv_bfloat16* __restrict__ wih, __nv_bfloat16* __restrict__ wil,
                                 __nv_bfloat16* __restrict__ whh, __nv_bfloat16* __restrict__ whl,
                                 float* __restrict__ gb0)
{
    int b = blockIdx.x, t = threadIdx.x;
    if (b == 3200) {
        #pragma unroll
        for (int k = 0; k < 4; k++) {
            int col = k * 256 + t;
            int g = col & 3, u = col >> 2;
            gb0[col] = b_ih[g * 512 + u] + b_hh[g * 512 + u];
        }
        return;
    }
    float v;
    __nv_bfloat16 *hi, *lo;
    int idx;
    if (b < 128)       { idx = b * 256 + t;          v = gcn_w[idx]; hi = gwh; lo = gwl; }
    else if (b < 640)  { idx = (b - 128) * 256 + t;  v = p1w[idx];   hi = p1h; lo = p1l; }
    else if (b < 1152) { idx = (b - 640) * 256 + t;  v = p2w[idx];   hi = p2h; lo = p2l; }
    else {
        const float* W; int ldw;
        if (b < 2176) { idx = (b - 1152) * 256 + t; W = w_ih; ldw = 256; hi = wih; lo = wil; }
        else          { idx = (b - 2176) * 256 + t; W = w_hh; ldw = 512; hi = whh; lo = whl; }
        int orow = idx >> 8, c = idx & 255;
        int u = orow >> 2, g = orow & 3;           // packed col = u*4+g
        v = W[(size_t)(g * 512 + u) * ldw + c];
    }
    __nv_bfloat16 h = __float2bfloat16(v);
    hi[idx] = h;
    lo[idx] = __float2bfloat16(v - __bfloat162float(h));
}

// ================= gb1 = gb0 + rvec (packed) =================
__global__ void gb1_kernel(const float* __restrict__ w_hh,
                           const float* __restrict__ sg,
                           const float* __restrict__ gb0,
                           float* __restrict__ gb1)
{
    int col = blockIdx.x * 256 + threadIdx.x;  // 1024
    int g = col & 3, u = col >> 2;
    const float* w = w_hh + (size_t)(g * 512 + u) * 512 + 256;
    float s = 0.0f;
    #pragma unroll 8
    for (int k = 0; k < 256; k++) s += w[k] * sg[k];
    gb1[col] = gb0[col] + s;
}

// ================= unified mma.sync bf16x3 GEMM ==============================
// 64x128 CTA tile, 8 warps (2m x 4n), K-chunks of 64, 3-stage cp.async,
// 2 CTAs/SM. blockIdx.z = split-K partition (K per partition, partial -> C+z*ps).
enum { EPI_RAW0 = 0, EPI_RELU = 1, EPI_CELL0 = 4, EPI_CELL = 5 };

__device__ __forceinline__ void cp16(uint32_t daddr, const void* g) {
    asm volatile("cp.async.cg.shared.global [%0], [%1], 16;" :: "r"(daddr), "l"(g));
}

__device__ __forceinline__ void stage_load(char* sa, char* sb,
                                           const __nv_bfloat16* __restrict__ Asrc,
                                           const __nv_bfloat16* __restrict__ Bsrc,
                                           int lda, int ldb, int bm, int bn,
                                           int koff, int tid)
{
    #pragma unroll
    for (int i = 0; i < 2; i++) {
        int idx = i * 256 + tid;
        int row = idx >> 3, ch = idx & 7;
        uint32_t off = (uint32_t)(row * 128 + ch * 16);
        uint32_t sw  = off ^ ((off >> 3) & 0x70);
        cp16(smem_u32(sa + sw), Asrc + (size_t)(bm + row) * lda + koff + ch * 8);
    }
    #pragma unroll
    for (int i = 0; i < 4; i++) {
        int idx = i * 256 + tid;
        int row = idx >> 3, ch = idx & 7;
        uint32_t off = (uint32_t)(row * 128 + ch * 16);
        uint32_t sw  = off ^ ((off >> 3) & 0x70);
        cp16(smem_u32(sb + sw), Bsrc + (size_t)(bn + row) * ldb + koff + ch * 8);
    }
}

template <int EPI>
__device__ __forceinline__ void cell_store(int r, int u,
                                           float gi, float gf, float gg, float go,
                                           float* __restrict__ cvec,
                                           const float* __restrict__ qg,
                                           float* __restrict__ hout,
                                           __nv_bfloat16* __restrict__ outh,
                                           __nv_bfloat16* __restrict__ outl)
{
    size_t idx = (size_t)r * 256 + u;
    float cp = (EPI == EPI_CELL) ? cvec[idx] : 0.0f;
    float cn = sigf(gf) * cp + sigf(gi) * tanhf(gg);
    cvec[idx] = cn;
    float hv = qg[idx] + sigf(go) * tanhf(cn);
    hout[idx] = hv;
    __nv_bfloat16 h = __float2bfloat16(hv);
    outh[idx] = h;
    outl[idx] = __float2bfloat16(hv - __bfloat162float(h));
}

template <int EPI>
__device__ __forceinline__ void epi_store(int gm, int gn, float v,
                                          float* __restrict__ C, int ldc,
                                          const float* __restrict__ bias,
                                          __nv_bfloat16* __restrict__ outh,
                                          __nv_bfloat16* __restrict__ outl)
{
    if (EPI == EPI_RAW0) {
        C[(size_t)gm * ldc + gn] = v;
    } else {  // EPI_RELU
        float o = fmaxf(v + bias[gn], 0.0f);
        size_t idx = (size_t)gm * ldc + gn;
        __nv_bfloat16 h = __float2bfloat16(o);
        outh[idx] = h;
        outl[idx] = __float2bfloat16(o - __bfloat162float(h));
    }
}

template <int EPI>
__global__ __launch_bounds__(256, 2)
void mma_gemm(const __nv_bfloat16* __restrict__ Ah, const __nv_bfloat16* __restrict__ Al,
              int lda,
              const __nv_bfloat16* __restrict__ Bh, const __nv_bfloat16* __restrict__ Bl,
              int ldb, int K, size_t pstride,
              float* __restrict__ C, int ldc,
              const float* __restrict__ bias, const float* __restrict__ extra,
              __nv_bfloat16* __restrict__ outh, __nv_bfloat16* __restrict__ outl,
              float* __restrict__ cvec, float* __restrict__ hout)
{
    constexpr int MI = 2;
    constexpr int ASZ = 64 * 128;          // 8 KB
    constexpr int STAGE = ASZ + 16384;     // 24 KB
    extern __shared__ char smem[];         // 3 stages = 72 KB
    const int tid  = threadIdx.x;
    const int wid  = tid >> 5;
    const int lane = tid & 31;
    const int bm = blockIdx.y * 64;
    const int bn = blockIdx.x * 128;
    const int zoff = blockIdx.z * K;
    C += (size_t)blockIdx.z * pstride;
    const int warp_m = wid & 1;
    const int warp_n = wid >> 1;

    float acc[MI][4][4];
    #pragma unroll
    for (int mi = 0; mi < MI; mi++)
        #pragma unroll
        for (int nj = 0; nj < 4; nj++)
            #pragma unroll
            for (int q = 0; q < 4; q++) acc[mi][nj][q] = 0.0f;

    const int a_row_off = (lane & 7) + ((lane >> 3) & 1) * 8;
    const int a_ch_off  = lane >> 4;
    const int b_row_off = (lane >> 4) * 8 + (lane & 7);   // x4: nj-sub from lane>>4
    const int b_ch_off  = (lane >> 3) & 1;

    const int nk = K >> 6;
    const int nt = 3 * nk;

    auto pick = [&](int c, const __nv_bfloat16*& As, const __nv_bfloat16*& Bs, int& koff) {
        int kc = c;
        As = Ah; Bs = Bh;
        if (c >= 2 * nk)  { As = Al; kc = c - 2 * nk; }
        else if (c >= nk) { Bs = Bl; kc = c - nk; }
        koff = kc * 64 + zoff;
    };

    // prologue: stages 0 and 1
    {
        const __nv_bfloat16 *As, *Bs; int koff;
        pick(0, As, Bs, koff);
        stage_load(smem, smem + ASZ, As, Bs, lda, ldb, bm, bn, koff, tid);
        asm volatile("cp.async.commit_group;");
        pick(1, As, Bs, koff);
        stage_load(smem + STAGE, smem + STAGE + ASZ, As, Bs, lda, ldb, bm, bn, koff, tid);
        asm volatile("cp.async.commit_group;");
    }

    int buf = 0;
    for (int c = 0; c < nt; c++) {
        if (c + 1 < nt) asm volatile("cp.async.wait_group 1;");
        else            asm volatile("cp.async.wait_group 0;");
        __syncthreads();

        const uint32_t sa_base = smem_u32(smem + buf * STAGE);
        const uint32_t sb_base = sa_base + ASZ;

        #pragma unroll
        for (int ks = 0; ks < 4; ks++) {
            uint32_t a[MI][4];
            #pragma unroll
            for (int mi = 0; mi < MI; mi++) {
                uint32_t row = warp_m * 32 + mi * 16 + a_row_off;
                uint32_t ch  = ks * 2 + a_ch_off;
                uint32_t off = row * 128 + ch * 16;
                uint32_t addr = sa_base + (off ^ ((off >> 3) & 0x70));
                asm volatile("ldmatrix.sync.aligned.m8n8.x4.shared.b16 {%0,%1,%2,%3}, [%4];"
                             : "=r"(a[mi][0]), "=r"(a[mi][1]), "=r"(a[mi][2]), "=r"(a[mi][3])
                             : "r"(addr));
            }
            uint32_t b[4][2];
            #pragma unroll
            for (int njp = 0; njp < 2; njp++) {
                uint32_t row = warp_n * 32 + njp * 16 + b_row_off;
                uint32_t ch  = ks * 2 + b_ch_off;
                uint32_t off = row * 128 + ch * 16;
                uint32_t addr = sb_base + (off ^ ((off >> 3) & 0x70));
                asm volatile("ldmatrix.sync.aligned.m8n8.x4.shared.b16 {%0,%1,%2,%3}, [%4];"
                             : "=r"(b[njp * 2][0]), "=r"(b[njp * 2][1]),
                               "=r"(b[njp * 2 + 1][0]), "=r"(b[njp * 2 + 1][1])
                             : "r"(addr));
            }
            #pragma unroll
            for (int mi = 0; mi < MI; mi++)
                #pragma unroll
                for (int nj = 0; nj < 4; nj++)
                    asm volatile(
                        "mma.sync.aligned.m16n8k16.row.col.f32.bf16.bf16.f32 "
                        "{%0,%1,%2,%3}, {%4,%5,%6,%7}, {%8,%9}, {%0,%1,%2,%3};"
                        : "+f"(acc[mi][nj][0]), "+f"(acc[mi][nj][1]),
                          "+f"(acc[mi][nj][2]), "+f"(acc[mi][nj][3])
                        : "r"(a[mi][0]), "r"(a[mi][1]), "r"(a[mi][2]), "r"(a[mi][3]),
                          "r"(b[nj][0]), "r"(b[nj][1]));
        }

        if (c + 2 < nt) {
            const __nv_bfloat16 *As, *Bs; int koff;
            pick(c + 2, As, Bs, koff);
            int nb = buf + 2; if (nb >= 3) nb -= 3;
            char* base = smem + nb * STAGE;
            stage_load(base, base + ASZ, As, Bs, lda, ldb, bm, bn, koff, tid);
            asm volatile("cp.async.commit_group;");
        }
        buf++; if (buf == 3) buf = 0;
    }

    if (EPI == EPI_CELL0 || EPI == EPI_CELL) {
        #pragma unroll
        for (int mi = 0; mi < MI; mi++) {
            int m0 = bm + warp_m * 32 + mi * 16 + (lane >> 2);
            #pragma unroll
            for (int nj = 0; nj < 4; nj++) {
                int n0 = bn + warp_n * 32 + nj * 8 + (lane & 3) * 2;
                float v0 = acc[mi][nj][0], v1 = acc[mi][nj][1];
                float v2 = acc[mi][nj][2], v3 = acc[mi][nj][3];
                if (EPI == EPI_CELL0) {
                    *(float2*)(C + (size_t)m0 * ldc + n0)       = make_float2(v0, v1);
                    *(float2*)(C + (size_t)(m0 + 8) * ldc + n0) = make_float2(v2, v3);
                } else {
                    float2 x0 = *(const float2*)(C + (size_t)m0 * ldc + n0);
                    float2 x1 = *(const float2*)(C + (size_t)(m0 + 8) * ldc + n0);
                    v0 += x0.x; v1 += x0.y; v2 += x1.x; v3 += x1.y;
                }
                float bb0 = bias[n0], bb1 = bias[n0 + 1];
                v0 += bb0; v1 += bb1; v2 += bb0; v3 += bb1;
                float e0 = __shfl_xor_sync(0xFFFFFFFFu, v0, 1);
                float e1 = __shfl_xor_sync(0xFFFFFFFFu, v1, 1);
                float e2 = __shfl_xor_sync(0xFFFFFFFFu, v2, 1);
                float e3 = __shfl_xor_sync(0xFFFFFFFFu, v3, 1);
                if ((lane & 1) == 0) {
                    int u = n0 >> 2;
                    cell_store<EPI>(m0,     u, v0, v1, e0, e1, cvec, extra, hout, outh, outl);
                    cell_store<EPI>(m0 + 8, u, v2, v3, e2, e3, cvec, extra, hout, outh, outl);
                }
            }
        }
    } else {
        #pragma unroll
        for (int mi = 0; mi < MI; mi++) {
            int m0 = bm + warp_m * 32 + mi * 16 + (lane >> 2);
            #pragma unroll
            for (int nj = 0; nj < 4; nj++) {
                int n0 = bn + warp_n * 32 + nj * 8 + (lane & 3) * 2;
                epi_store<EPI>(m0,     n0,     acc[mi][nj][0], C, ldc, bias, outh, outl);
                epi_store<EPI>(m0,     n0 + 1, acc[mi][nj][1], C, ldc, bias, outh, outl);
                epi_store<EPI>(m0 + 8, n0,     acc[mi][nj][2], C, ldc, bias, outh, outl);
                epi_store<EPI>(m0 + 8, n0 + 1, acc[mi][nj][3], C, ldc, bias, outh, outl);
            }
        }
    }
}

// ================= NB combine: tanh((p0+p1+64b)*inv), remap, bf16 split ======
__global__ void nb_combine_kernel(const float* __restrict__ P,
                                  const float* __restrict__ bias,
                                  const float* __restrict__ inv,
                                  float* __restrict__ QNB,
                                  __nv_bfloat16* __restrict__ hi,
                                  __nv_bfloat16* __restrict__ lo)
{
    int r = blockIdx.x;            // out row 0..4100
    int t = threadIdx.x;           // 256
    int src = 2 * r + (t >> 7);
    int col = t & 127;
    size_t pidx = (size_t)src * 128 + col;
    float v = P[pidx] + P[PSTRIDE_NB + pidx];
    float o = tanhf((v + 64.0f * bias[col]) * inv[src]);
    size_t idx = (size_t)r * 256 + t;
    QNB[idx] = o;
    __nv_bfloat16 h = __float2bfloat16(o);
    hi[idx] = h;
    lo[idx] = __float2bfloat16(o - __bfloat162float(h));
}

// ================= layernorm over RES partials + bf16 split =================
__global__ void ln_split_kernel(const float* __restrict__ ZP,
                                const float* __restrict__ QNB,
                                const float* __restrict__ p2b,
                                const float* __restrict__ g,
                                const float* __restrict__ bb,
                                float* __restrict__ out,
                                __nv_bfloat16* __restrict__ hi,
                                __nv_bfloat16* __restrict__ lo)
{
    __shared__ float sbuf[256];
    int r = blockIdx.x, t = threadIdx.x;
    size_t idx = (size_t)r * 256 + t;
    float z = ZP[idx] + ZP[PSTRIDE_RES + idx] + p2b[t] + QNB[idx];
    float mu = block_sum256(z, sbuf) * (1.0f / 256.0f);
    float d = z - mu;
    float var = block_sum256(d * d, sbuf) * (1.0f / 255.0f);
    float o = g[t] * d / (sqrtf(var) + 1e-6f) + bb[t];
    out[idx] = o;
    __nv_bfloat16 h = __float2bfloat16(o);
    hi[idx] = h;
    lo[idx] = __float2bfloat16(o - __bfloat162float(h));
}

// ================= SG (mean of LN rows 4096..4100) + SN =================
__global__ void sg_sn_kernel(const float* __restrict__ QG,
                             float* __restrict__ SG, float* __restrict__ SN)
{
    __shared__ float sbuf[256];
    int t = threadIdx.x;
    float s = 0.f;
    #pragma unroll
    for (int r = 0; r < 5; r++) s += QG[(size_t)(4096 + r) * 256 + t];
    float v = s * 0.2f;
    SG[t] = v;
    float n2 = block_sum256(v * v, sbuf);
    SN[t] = v / fmaxf(sqrtf(n2), 1e-12f);
}

// ================= final cosine similarity =================
__global__ void final_kernel(const float* __restrict__ h,
                             const float* __restrict__ sn,
                             float* __restrict__ out)
{
    __shared__ float sbuf[256];
    int b = blockIdx.x, t = threadIdx.x;
    float v = h[(size_t)b * 256 + t];
    float dot = block_sum256(v * sn[t], sbuf);
    float n2  = block_sum256(v * v, sbuf);
    if (t == 0) out[b] = dot / fmaxf(sqrtf(n2), 1e-12f);
}

// ================= launch =================
extern "C" void kernel_launch(void* const* d_in, const int* in_sizes, int n_in,
                              void* d_out, int out_size)
{
    (void)in_sizes; (void)n_in; (void)out_size;
    const int*   q_l_conn = (const int*)  d_in[2];
    const int*   q_l_deg  = (const int*)  d_in[3];
    const int*   q_r_conn = (const int*)  d_in[4];
    const int*   q_r_deg  = (const int*)  d_in[5];
    const int*   s_l_conn = (const int*)  d_in[6];
    const int*   s_l_deg  = (const int*)  d_in[7];
    const int*   s_r_conn = (const int*)  d_in[8];
    const int*   s_r_deg  = (const int*)  d_in[9];
    const float* emb      = (const float*)d_in[10];
    const float* gcn_w    = (const float*)d_in[11];
    const float* gcn_bias = (const float*)d_in[12];
    const float* proj1_w  = (const float*)d_in[13];
    const float* proj1_b  = (const float*)d_in[14];
    const float* proj2_w  = (const float*)d_in[15];
    const float* proj2_b  = (const float*)d_in[16];
    const float* ln_g     = (const float*)d_in[17];
    const float* ln_b     = (const float*)d_in[18];
    const float* w_ih     = (const float*)d_in[19];
    const float* w_hh     = (const float*)d_in[20];
    const float* b_ih     = (const float*)d_in[21];
    const float* b_hh     = (const float*)d_in[22];
    float* out = (float*)d_out;

    float* S = nullptr;
    cudaGetSymbolAddress((void**)&S, g_scratch);
    __nv_bfloat16* BF = nullptr;
    cudaGetSymbolAddress((void**)&BF, g_bf);

    float* INVQ = S + O_INVQ;  float* QNBP = S + O_QNBP;  float* QNB = S + O_QNB;
    float* ZP   = S + O_ZP;    float* QG   = S + O_QG;
    float* SG   = S + O_SG;    float* SN   = S + O_SN;    float* XW = S + O_XW;
    float* GB0  = S + O_GB0;   float* GB1  = S + O_GB1;
    float* C    = S + O_C;     float* H    = S + O_H;

    __nv_bfloat16* BQH = BF + B_BUFQH;  __nv_bfloat16* BQL = BF + B_BUFQL;
    __nv_bfloat16* QNBH = BF + B_QNBH;  __nv_bfloat16* QNBL = BF + B_QNBL;
    __nv_bfloat16* HQH = BF + B_HQH;    __nv_bfloat16* HQL = BF + B_HQL;
    __nv_bfloat16* QGH = BF + B_QGH;    __nv_bfloat16* QGL = BF + B_QGL;
    __nv_bfloat16* HH  = BF + B_HH;     __nv_bfloat16* HL  = BF + B_HL;
    __nv_bfloat16* GWH = BF + B_GWH;    __nv_bfloat16* GWL = BF + B_GWL;
    __nv_bfloat16* P1H = BF + B_P1H;    __nv_bfloat16* P1L = BF + B_P1L;
    __nv_bfloat16* P2H = BF + B_P2H;    __nv_bfloat16* P2L = BF + B_P2L;
    __nv_bfloat16* WIHH = BF + B_WIHH;  __nv_bfloat16* WIHL = BF + B_WIHL;
    __nv_bfloat16* WHHH = BF + B_WHHH;  __nv_bfloat16* WHHL = BF + B_WHHL;

    const int SM3 = 3 * (64 * 128 + 16384);  // 73728
    cudaFuncSetAttribute(mma_gemm<EPI_RAW0>,  cudaFuncAttributeMaxDynamicSharedMemorySize, SM3);
    cudaFuncSetAttribute(mma_gemm<EPI_RELU>,  cudaFuncAttributeMaxDynamicSharedMemorySize, SM3);
    cudaFuncSetAttribute(mma_gemm<EPI_CELL0>, cudaFuncAttributeMaxDynamicSharedMemorySize, SM3);
    cudaFuncSetAttribute(mma_gemm<EPI_CELL>,  cudaFuncAttributeMaxDynamicSharedMemorySize, SM3);

    // 1) weight splits + gb0, gathers (query + support rows 8192..8201)
    split_all_kernel<<<3201, 256>>>(gcn_w, proj1_w, proj2_w, w_ih, w_hh, b_ih, b_hh,
                                    GWH, GWL, P1H, P1L, P2H, P2L,
                                    WIHH, WIHL, WHHH, WHHL, GB0);
    gather_all_kernel<<<8202, 128>>>(q_l_conn, q_l_deg, q_r_conn, q_r_deg,
                                     s_l_conn, s_l_deg, s_r_conn, s_r_deg,
                                     emb, BQH, BQL, INVQ);

    // 2) GCN split-K=2 (129x2 = 258 CTAs) -> raw partials, then combine
    mma_gemm<EPI_RAW0><<<dim3(1, 129, 2), 256, SM3>>>(
        BQH, BQL, 256, GWH, GWL, 256, 128, PSTRIDE_NB, QNBP, 128,
        nullptr, nullptr, nullptr, nullptr, nullptr, nullptr);
    nb_combine_kernel<<<4101, 256>>>(QNBP, gcn_bias, INVQ, QNB, QNBH, QNBL);

    // 3) proj1 (264 CTAs), proj2 split-K=2 (264 CTAs), LN folds partial sum
    mma_gemm<EPI_RELU><<<dim3(4, 66), 256, SM3>>>(
        QNBH, QNBL, 256, P1H, P1L, 256, 256, 0, nullptr, 512,
        proj1_b, nullptr, HQH, HQL, nullptr, nullptr);
    mma_gemm<EPI_RAW0><<<dim3(2, 66, 2), 256, SM3>>>(
        HQH, HQL, 512, P2H, P2L, 512, 256, PSTRIDE_RES, ZP, 256,
        nullptr, nullptr, nullptr, nullptr, nullptr, nullptr);
    ln_split_kernel<<<4101, 256>>>(ZP, QNB, proj2_b, ln_g, ln_b, QG, QGH, QGL);

    // 4) support vector + gb1
    sg_sn_kernel<<<1, 256>>>(QG, SG, SN);
    gb1_kernel<<<4, 256>>>(w_hh, SG, GB0, GB1);

    // 5) LSTM: GEMM + fused cell epilogues (512 CTAs each)
    mma_gemm<EPI_CELL0><<<dim3(8, 64), 256, SM3>>>(
        QGH, QGL, 256, WIHH, WIHL, 256, 256, 0, XW, 1024,
        GB0, QG, HH, HL, C, H);
    for (int t = 1; t < 4; t++) {
        mma_gemm<EPI_CELL><<<dim3(8, 64), 256, SM3>>>(
            HH, HL, 256, WHHH, WHHL, 256, 256, 0, XW, 1024,
            GB1, QG, HH, HL, C, H);
    }

    // 6) cosine similarity
    final_kernel<<<4096, 256>>>(H, SN, out);
}

// round 12
// speedup vs baseline: 1.9981x; 1.3698x over previous
#include <cuda_runtime.h>
#include <cuda_fp16.h>
#include <math.h>
#include <stdint.h>

// ---------------------------------------------------------------------------
// EmbedMatcher on GB300 (sm_103 plain PTX -> mma.sync fp16 tensor cores).
//  - fp16 single-segment GEMMs (fp32 accumulate): unit roundoff 2^-12 ~ 2.4e-4,
//    validated headroom vs 1e-3 (bf16x3 measured exactly unit-roundoff 7e-6).
//  - 64x128 CTA tiles, 2 CTAs/SM, 3-stage cp.async, 1 sync/chunk.
//  - Split-K=2 on RES (folded into ln_split). NB epilogue in-GEMM.
//  - Gate-interleaved packing: LSTM cell fused into GEMM epilogue.
//  - Dead-gate elimination (N 2048->1024) + rank-1 support factorization.
// ---------------------------------------------------------------------------

__device__ __forceinline__ uint32_t smem_u32(const void* p) {
    uint32_t a;
    asm("{ .reg .u64 t; cvta.to.shared.u64 t, %1; cvt.u32.u64 %0, t; }"
        : "=r"(a) : "l"(p));
    return a;
}

// ================= fp32 scratch =================
constexpr size_t PSTRIDE_RES = 4224UL * 256;

constexpr size_t N_INVQ = 8320;
constexpr size_t N_ZP   = 2 * PSTRIDE_RES;
constexpr size_t N_QG   = 4224UL * 256;
constexpr size_t N_SG   = 256;
constexpr size_t N_SN   = 256;
constexpr size_t N_XW   = 4096UL * 1024;
constexpr size_t N_GB0  = 1024;
constexpr size_t N_GB1  = 1024;
constexpr size_t N_C    = 4096UL * 256;
constexpr size_t N_H    = 4096UL * 256;

constexpr size_t O_INVQ = 0;
constexpr size_t O_ZP   = O_INVQ + N_INVQ;
constexpr size_t O_QG   = O_ZP   + N_ZP;
constexpr size_t O_SG   = O_QG   + N_QG;
constexpr size_t O_SN   = O_SG   + N_SG;
constexpr size_t O_XW   = O_SN   + N_SN;
constexpr size_t O_GB0  = O_XW   + N_XW;
constexpr size_t O_GB1  = O_GB0  + N_GB0;
constexpr size_t O_C    = O_GB1  + N_GB1;
constexpr size_t O_H    = O_C    + N_C;
constexpr size_t SCRATCH_TOTAL = O_H + N_H;
__device__ float g_scratch[SCRATCH_TOTAL];

// ================= fp16 scratch =================
constexpr size_t H_BUFQ = 0;
constexpr size_t H_QNB  = H_BUFQ + 8320UL * 256;
constexpr size_t H_HQ   = H_QNB  + 4224UL * 256;
constexpr size_t H_QG   = H_HQ   + 4224UL * 512;
constexpr size_t H_HH   = H_QG   + 4224UL * 256;
constexpr size_t H_GW   = H_HH   + 4096UL * 256;
constexpr size_t H_P1   = H_GW   + 128UL * 256;
constexpr size_t H_P2   = H_P1   + 512UL * 256;
constexpr size_t H_WIH  = H_P2   + 256UL * 512;
constexpr size_t H_WHH  = H_WIH  + 1024UL * 256;
constexpr size_t HF_TOTAL = H_WHH + 1024UL * 256;
__device__ __align__(128) __half g_hf[HF_TOTAL];

// ================= helpers =================
__device__ __forceinline__ float sigf(float x) { return 1.0f / (1.0f + expf(-x)); }

__device__ __forceinline__ float block_sum256(float v, float* sbuf) {
    int t = threadIdx.x;
    sbuf[t] = v;
    __syncthreads();
    #pragma unroll
    for (int s = 128; s > 0; s >>= 1) {
        if (t < s) sbuf[t] += sbuf[t + s];
        __syncthreads();
    }
    float r = sbuf[0];
    __syncthreads();
    return r;
}

// ================= fused gather (query + support), float4 loads ==============
__global__ void gather_all_kernel(const int* __restrict__ qlc, const int* __restrict__ qld,
                                  const int* __restrict__ qrc, const int* __restrict__ qrd,
                                  const int* __restrict__ slc, const int* __restrict__ sld,
                                  const int* __restrict__ src_, const int* __restrict__ srd,
                                  const float* __restrict__ emb,
                                  __half* __restrict__ bq,
                                  float* __restrict__ invq)
{
    __shared__ int sc[128];
    __shared__ float4 red[2][4][32];
    int b = blockIdx.x;
    const int* conn; const int* deg; int r, row;
    if (b < 4096)      { r = b;        conn = qlc;  deg = qld; row = 2 * r; }
    else if (b < 8192) { r = b - 4096; conn = qrc;  deg = qrd; row = 2 * r + 1; }
    else if (b < 8197) { r = b - 8192; conn = slc;  deg = sld; row = 8192 + 2 * r; }
    else               { r = b - 8197; conn = src_; deg = srd; row = 8192 + 2 * r + 1; }
    int t = threadIdx.x;  // 128
    int w = t >> 5, l = t & 31;
    sc[t] = conn[r * 128 + t];
    __syncthreads();
    float4 a0 = make_float4(0.f, 0.f, 0.f, 0.f);
    float4 a1 = make_float4(0.f, 0.f, 0.f, 0.f);
    #pragma unroll 4
    for (int i = 0; i < 16; i++) {
        int n = w * 16 + i;
        float4 v0 = __ldg((const float4*)(emb + (size_t)sc[2 * n]     * 128) + l);
        float4 v1 = __ldg((const float4*)(emb + (size_t)sc[2 * n + 1] * 128) + l);
        a0.x += v0.x; a0.y += v0.y; a0.z += v0.z; a0.w += v0.w;
        a1.x += v1.x; a1.y += v1.y; a1.z += v1.z; a1.w += v1.w;
    }
    red[0][w][l] = a0;
    red[1][w][l] = a1;
    __syncthreads();
    if (t < 64) {
        int which = t >> 5, ll = t & 31;
        float4 p0 = red[which][0][ll], p1 = red[which][1][ll];
        float4 p2 = red[which][2][ll], p3 = red[which][3][ll];
        float s[4];
        s[0] = p0.x + p1.x + p2.x + p3.x;
        s[1] = p0.y + p1.y + p2.y + p3.y;
        s[2] = p0.z + p1.z + p2.z + p3.z;
        s[3] = p0.w + p1.w + p2.w + p3.w;
        size_t base = (size_t)row * 256 + which * 128 + ll * 4;
        #pragma unroll
        for (int j = 0; j < 4; j++) bq[base + j] = __float2half(s[j]);
    }
    if (t == 0) invq[row] = 1.0f / (float)max(deg[r], 1);
}

// ================= merged weight conversion + gb0 =============================
// blocks: [0,128) gcn | [128,640) p1 | [640,1152) p2 | [1152,2176) w_ih packed
//         [2176,3200) w_hh packed | 3200 gb0
__global__ void split_all_kernel(const float* __restrict__ gcn_w,
                                 const float* __restrict__ p1w,
                                 const float* __restrict__ p2w,
                                 const float* __restrict__ w_ih,
                                 const float* __restrict__ w_hh,
                                 const float* __restrict__ b_ih,
                                 const float* __restrict__ b_hh,
                                 __half* __restrict__ gw,
                                 __half* __restrict__ p1,
                                 __half* __restrict__ p2,
                                 __half* __restrict__ wih,
                                 __half* __restrict__ whh,
                                 float* __restrict__ gb0)
{
    int b = blockIdx.x, t = threadIdx.x;
    if (b == 3200) {
        #pragma unroll
        for (int k = 0; k < 4; k++) {
            int col = k * 256 + t;
            int g = col & 3, u = col >> 2;
            gb0[col] = b_ih[g * 512 + u] + b_hh[g * 512 + u];
        }
        return;
    }
    float v;
    __half* dst;
    int idx;
    if (b < 128)       { idx = b * 256 + t;          v = gcn_w[idx]; dst = gw; }
    else if (b < 640)  { idx = (b - 128) * 256 + t;  v = p1w[idx];   dst = p1; }
    else if (b < 1152) { idx = (b - 640) * 256 + t;  v = p2w[idx];   dst = p2; }
    else {
        const float* W; int ldw;
        if (b < 2176) { idx = (b - 1152) * 256 + t; W = w_ih; ldw = 256; dst = wih; }
        else          { idx = (b - 2176) * 256 + t; W = w_hh; ldw = 512; dst = whh; }
        int orow = idx >> 8, c = idx & 255;
        int u = orow >> 2, g = orow & 3;           // packed col = u*4+g
        v = W[(size_t)(g * 512 + u) * ldw + c];
    }
    dst[idx] = __float2half(v);
}

// ================= gb1 = gb0 + rvec (packed) =================
__global__ void gb1_kernel(const float* __restrict__ w_hh,
                           const float* __restrict__ sg,
                           const float* __restrict__ gb0,
                           float* __restrict__ gb1)
{
    int col = blockIdx.x * 256 + threadIdx.x;  // 1024
    int g = col & 3, u = col >> 2;
    const float* w = w_hh + (size_t)(g * 512 + u) * 512 + 256;
    float s = 0.0f;
    #pragma unroll 8
    for (int k = 0; k < 256; k++) s += w[k] * sg[k];
    gb1[col] = gb0[col] + s;
}

// ================= unified mma.sync fp16 GEMM ================================
// 64x128 CTA tile, 8 warps (2m x 4n), K-chunks of 64, 3-stage cp.async,
// 2 CTAs/SM. blockIdx.z = split-K partition (partial -> C + z*pstride).
enum { EPI_RAW0 = 0, EPI_RELU = 1, EPI_NB = 3, EPI_CELL0 = 4, EPI_CELL = 5 };

__device__ __forceinline__ void cp16(uint32_t daddr, const void* g) {
    asm volatile("cp.async.cg.shared.global [%0], [%1], 16;" :: "r"(daddr), "l"(g));
}

__device__ __forceinline__ void stage_load(char* sa, char* sb,
                                           const __half* __restrict__ Asrc,
                                           const __half* __restrict__ Bsrc,
                                           int lda, int ldb, int bm, int bn,
                                           int koff, int tid)
{
    #pragma unroll
    for (int i = 0; i < 2; i++) {
        int idx = i * 256 + tid;
        int row = idx >> 3, ch = idx & 7;
        uint32_t off = (uint32_t)(row * 128 + ch * 16);
        uint32_t sw  = off ^ ((off >> 3) & 0x70);
        cp16(smem_u32(sa + sw), Asrc + (size_t)(bm + row) * lda + koff + ch * 8);
    }
    #pragma unroll
    for (int i = 0; i < 4; i++) {
        int idx = i * 256 + tid;
        int row = idx >> 3, ch = idx & 7;
        uint32_t off = (uint32_t)(row * 128 + ch * 16);
        uint32_t sw  = off ^ ((off >> 3) & 0x70);
        cp16(smem_u32(sb + sw), Bsrc + (size_t)(bn + row) * ldb + koff + ch * 8);
    }
}

template <int EPI>
__device__ __forceinline__ void cell_store(int r, int u,
                                           float gi, float gf, float gg, float go,
                                           float* __restrict__ cvec,
                                           const float* __restrict__ qg,
                                           float* __restrict__ hout,
                                           __half* __restrict__ outh)
{
    size_t idx = (size_t)r * 256 + u;
    float cp = (EPI == EPI_CELL) ? cvec[idx] : 0.0f;
    float cn = sigf(gf) * cp + sigf(gi) * tanhf(gg);
    cvec[idx] = cn;
    float hv = qg[idx] + sigf(go) * tanhf(cn);
    hout[idx] = hv;
    outh[idx] = __float2half(hv);
}

template <int EPI>
__device__ __forceinline__ void epi_store(int gm, int gn, float v,
                                          float* __restrict__ C, int ldc,
                                          const float* __restrict__ bias,
                                          const float* __restrict__ extra,
                                          __half* __restrict__ outh)
{
    if (EPI == EPI_RAW0) {
        C[(size_t)gm * ldc + gn] = v;
    } else if (EPI == EPI_RELU) {
        float o = fmaxf(v + bias[gn], 0.0f);
        outh[(size_t)gm * ldc + gn] = __float2half(o);
    } else {  // EPI_NB: tanh((v + 64*bias)*inv[gm]); remap (8k x 128)->(4k x 256)
        float o = tanhf((v + 64.0f * bias[gn]) * extra[gm]);
        size_t idx = (size_t)(gm >> 1) * 256 + (size_t)(gm & 1) * 128 + gn;
        outh[idx] = __float2half(o);
    }
}

template <int EPI>
__global__ __launch_bounds__(256, 2)
void mma_gemm(const __half* __restrict__ A, int lda,
              const __half* __restrict__ B, int ldb,
              int K, size_t pstride,
              float* __restrict__ C, int ldc,
              const float* __restrict__ bias, const float* __restrict__ extra,
              __half* __restrict__ outh,
              float* __restrict__ cvec, float* __restrict__ hout)
{
    constexpr int MI = 2;
    constexpr int ASZ = 64 * 128;          // 8 KB
    constexpr int STAGE = ASZ + 16384;     // 24 KB
    extern __shared__ char smem[];         // 3 stages = 72 KB
    const int tid  = threadIdx.x;
    const int wid  = tid >> 5;
    const int lane = tid & 31;
    const int bm = blockIdx.y * 64;
    const int bn = blockIdx.x * 128;
    const int zoff = blockIdx.z * K;
    C += (size_t)blockIdx.z * pstride;
    const int warp_m = wid & 1;
    const int warp_n = wid >> 1;

    float acc[MI][4][4];
    #pragma unroll
    for (int mi = 0; mi < MI; mi++)
        #pragma unroll
        for (int nj = 0; nj < 4; nj++)
            #pragma unroll
            for (int q = 0; q < 4; q++) acc[mi][nj][q] = 0.0f;

    const int a_row_off = (lane & 7) + ((lane >> 3) & 1) * 8;
    const int a_ch_off  = lane >> 4;
    const int b_row_off = (lane >> 4) * 8 + (lane & 7);
    const int b_ch_off  = (lane >> 3) & 1;

    const int nt = K >> 6;

    // prologue: stages 0 and 1
    stage_load(smem, smem + ASZ, A, B, lda, ldb, bm, bn, zoff, tid);
    asm volatile("cp.async.commit_group;");
    if (nt > 1) {
        stage_load(smem + STAGE, smem + STAGE + ASZ, A, B, lda, ldb, bm, bn,
                   zoff + 64, tid);
        asm volatile("cp.async.commit_group;");
    }

    int buf = 0;
    for (int c = 0; c < nt; c++) {
        if (c + 1 < nt) asm volatile("cp.async.wait_group 1;");
        else            asm volatile("cp.async.wait_group 0;");
        __syncthreads();

        const uint32_t sa_base = smem_u32(smem + buf * STAGE);
        const uint32_t sb_base = sa_base + ASZ;

        #pragma unroll
        for (int ks = 0; ks < 4; ks++) {
            uint32_t a[MI][4];
            #pragma unroll
            for (int mi = 0; mi < MI; mi++) {
                uint32_t row = warp_m * 32 + mi * 16 + a_row_off;
                uint32_t ch  = ks * 2 + a_ch_off;
                uint32_t off = row * 128 + ch * 16;
                uint32_t addr = sa_base + (off ^ ((off >> 3) & 0x70));
                asm volatile("ldmatrix.sync.aligned.m8n8.x4.shared.b16 {%0,%1,%2,%3}, [%4];"
                             : "=r"(a[mi][0]), "=r"(a[mi][1]), "=r"(a[mi][2]), "=r"(a[mi][3])
                             : "r"(addr));
            }
            uint32_t b[4][2];
            #pragma unroll
            for (int njp = 0; njp < 2; njp++) {
                uint32_t row = warp_n * 32 + njp * 16 + b_row_off;
                uint32_t ch  = ks * 2 + b_ch_off;
                uint32_t off = row * 128 + ch * 16;
                uint32_t addr = sb_base + (off ^ ((off >> 3) & 0x70));
                asm volatile("ldmatrix.sync.aligned.m8n8.x4.shared.b16 {%0,%1,%2,%3}, [%4];"
                             : "=r"(b[njp * 2][0]), "=r"(b[njp * 2][1]),
                               "=r"(b[njp * 2 + 1][0]), "=r"(b[njp * 2 + 1][1])
                             : "r"(addr));
            }
            #pragma unroll
            for (int mi = 0; mi < MI; mi++)
                #pragma unroll
                for (int nj = 0; nj < 4; nj++)
                    asm volatile(
                        "mma.sync.aligned.m16n8k16.row.col.f32.f16.f16.f32 "
                        "{%0,%1,%2,%3}, {%4,%5,%6,%7}, {%8,%9}, {%0,%1,%2,%3};"
                        : "+f"(acc[mi][nj][0]), "+f"(acc[mi][nj][1]),
                          "+f"(acc[mi][nj][2]), "+f"(acc[mi][nj][3])
                        : "r"(a[mi][0]), "r"(a[mi][1]), "r"(a[mi][2]), "r"(a[mi][3]),
                          "r"(b[nj][0]), "r"(b[nj][1]));
        }

        if (c + 2 < nt) {
            int nb = buf + 2; if (nb >= 3) nb -= 3;
            char* base = smem + nb * STAGE;
            stage_load(base, base + ASZ, A, B, lda, ldb, bm, bn,
                       zoff + (c + 2) * 64, tid);
            asm volatile("cp.async.commit_group;");
        }
        buf++; if (buf == 3) buf = 0;
    }

    if (EPI == EPI_CELL0 || EPI == EPI_CELL) {
        #pragma unroll
        for (int mi = 0; mi < MI; mi++) {
            int m0 = bm + warp_m * 32 + mi * 16 + (lane >> 2);
            #pragma unroll
            for (int nj = 0; nj < 4; nj++) {
                int n0 = bn + warp_n * 32 + nj * 8 + (lane & 3) * 2;
                float v0 = acc[mi][nj][0], v1 = acc[mi][nj][1];
                float v2 = acc[mi][nj][2], v3 = acc[mi][nj][3];
                if (EPI == EPI_CELL0) {
                    *(float2*)(C + (size_t)m0 * ldc + n0)       = make_float2(v0, v1);
                    *(float2*)(C + (size_t)(m0 + 8) * ldc + n0) = make_float2(v2, v3);
                } else {
                    float2 x0 = *(const float2*)(C + (size_t)m0 * ldc + n0);
                    float2 x1 = *(const float2*)(C + (size_t)(m0 + 8) * ldc + n0);
                    v0 += x0.x; v1 += x0.y; v2 += x1.x; v3 += x1.y;
                }
                float bb0 = bias[n0], bb1 = bias[n0 + 1];
                v0 += bb0; v1 += bb1; v2 += bb0; v3 += bb1;
                float e0 = __shfl_xor_sync(0xFFFFFFFFu, v0, 1);
                float e1 = __shfl_xor_sync(0xFFFFFFFFu, v1, 1);
                float e2 = __shfl_xor_sync(0xFFFFFFFFu, v2, 1);
                float e3 = __shfl_xor_sync(0xFFFFFFFFu, v3, 1);
                if ((lane & 1) == 0) {
                    int u = n0 >> 2;
                    cell_store<EPI>(m0,     u, v0, v1, e0, e1, cvec, extra, hout, outh);
                    cell_store<EPI>(m0 + 8, u, v2, v3, e2, e3, cvec, extra, hout, outh);
                }
            }
        }
    } else {
        #pragma unroll
        for (int mi = 0; mi < MI; mi++) {
            int m0 = bm + warp_m * 32 + mi * 16 + (lane >> 2);
            #pragma unroll
            for (int nj = 0; nj < 4; nj++) {
                int n0 = bn + warp_n * 32 + nj * 8 + (lane & 3) * 2;
                epi_store<EPI>(m0,     n0,     acc[mi][nj][0], C, ldc, bias, extra, outh);
                epi_store<EPI>(m0,     n0 + 1, acc[mi][nj][1], C, ldc, bias, extra, outh);
                epi_store<EPI>(m0 + 8, n0,     acc[mi][nj][2], C, ldc, bias, extra, outh);
                epi_store<EPI>(m0 + 8, n0 + 1, acc[mi][nj][3], C, ldc, bias, extra, outh);
            }
        }
    }
}

// ================= layernorm over RES partials + fp16 out ====================
__global__ void ln_split_kernel(const float* __restrict__ ZP,
                                const __half* __restrict__ QNB,
                                const float* __restrict__ p2b,
                                const float* __restrict__ g,
                                const float* __restrict__ bb,
                                float* __restrict__ out,
                                __half* __restrict__ oh)
{
    __shared__ float sbuf[256];
    int r = blockIdx.x, t = threadIdx.x;
    size_t idx = (size_t)r * 256 + t;
    float z = ZP[idx] + ZP[PSTRIDE_RES + idx] + p2b[t] + __half2float(QNB[idx]);
    float mu = block_sum256(z, sbuf) * (1.0f / 256.0f);
    float d = z - mu;
    float var = block_sum256(d * d, sbuf) * (1.0f / 255.0f);
    float o = g[t] * d / (sqrtf(var) + 1e-6f) + bb[t];
    out[idx] = o;
    oh[idx] = __float2half(o);
}

// ================= SG (mean of LN rows 4096..4100) + SN =================
__global__ void sg_sn_kernel(const float* __restrict__ QG,
                             float* __restrict__ SG, float* __restrict__ SN)
{
    __shared__ float sbuf[256];
    int t = threadIdx.x;
    float s = 0.f;
    #pragma unroll
    for (int r = 0; r < 5; r++) s += QG[(size_t)(4096 + r) * 256 + t];
    float v = s * 0.2f;
    SG[t] = v;
    float n2 = block_sum256(v * v, sbuf);
    SN[t] = v / fmaxf(sqrtf(n2), 1e-12f);
}

// ================= final cosine similarity =================
__global__ void final_kernel(const float* __restrict__ h,
                             const float* __restrict__ sn,
                             float* __restrict__ out)
{
    __shared__ float sbuf[256];
    int b = blockIdx.x, t = threadIdx.x;
    float v = h[(size_t)b * 256 + t];
    float dot = block_sum256(v * sn[t], sbuf);
    float n2  = block_sum256(v * v, sbuf);
    if (t == 0) out[b] = dot / fmaxf(sqrtf(n2), 1e-12f);
}

// ================= launch =================
extern "C" void kernel_launch(void* const* d_in, const int* in_sizes, int n_in,
                              void* d_out, int out_size)
{
    (void)in_sizes; (void)n_in; (void)out_size;
    const int*   q_l_conn = (const int*)  d_in[2];
    const int*   q_l_deg  = (const int*)  d_in[3];
    const int*   q_r_conn = (const int*)  d_in[4];
    const int*   q_r_deg  = (const int*)  d_in[5];
    const int*   s_l_conn = (const int*)  d_in[6];
    const int*   s_l_deg  = (const int*)  d_in[7];
    const int*   s_r_conn = (const int*)  d_in[8];
    const int*   s_r_deg  = (const int*)  d_in[9];
    const float* emb      = (const float*)d_in[10];
    const float* gcn_w    = (const float*)d_in[11];
    const float* gcn_bias = (const float*)d_in[12];
    const float* proj1_w  = (const float*)d_in[13];
    const float* proj1_b  = (const float*)d_in[14];
    const float* proj2_w  = (const float*)d_in[15];
    const float* proj2_b  = (const float*)d_in[16];
    const float* ln_g     = (const float*)d_in[17];
    const float* ln_b     = (const float*)d_in[18];
    const float* w_ih     = (const float*)d_in[19];
    const float* w_hh     = (const float*)d_in[20];
    const float* b_ih     = (const float*)d_in[21];
    const float* b_hh     = (const float*)d_in[22];
    float* out = (float*)d_out;

    float* S = nullptr;
    cudaGetSymbolAddress((void**)&S, g_scratch);
    __half* HF = nullptr;
    cudaGetSymbolAddress((void**)&HF, g_hf);

    float* INVQ = S + O_INVQ;  float* ZP  = S + O_ZP;    float* QG = S + O_QG;
    float* SG   = S + O_SG;    float* SN  = S + O_SN;    float* XW = S + O_XW;
    float* GB0  = S + O_GB0;   float* GB1 = S + O_GB1;
    float* C    = S + O_C;     float* H   = S + O_H;

    __half* BQ  = HF + H_BUFQ;  __half* QNB = HF + H_QNB;
    __half* HQ  = HF + H_HQ;    __half* QGH = HF + H_QG;
    __half* HH  = HF + H_HH;    __half* GW  = HF + H_GW;
    __half* P1  = HF + H_P1;    __half* P2  = HF + H_P2;
    __half* WIH = HF + H_WIH;   __half* WHH = HF + H_WHH;

    const int SM3 = 3 * (64 * 128 + 16384);  // 73728
    cudaFuncSetAttribute(mma_gemm<EPI_RAW0>,  cudaFuncAttributeMaxDynamicSharedMemorySize, SM3);
    cudaFuncSetAttribute(mma_gemm<EPI_RELU>,  cudaFuncAttributeMaxDynamicSharedMemorySize, SM3);
    cudaFuncSetAttribute(mma_gemm<EPI_NB>,    cudaFuncAttributeMaxDynamicSharedMemorySize, SM3);
    cudaFuncSetAttribute(mma_gemm<EPI_CELL0>, cudaFuncAttributeMaxDynamicSharedMemorySize, SM3);
    cudaFuncSetAttribute(mma_gemm<EPI_CELL>,  cudaFuncAttributeMaxDynamicSharedMemorySize, SM3);

    // 1) weight fp16 conversion + gb0, gathers (query + support rows 8192..8201)
    split_all_kernel<<<3201, 256>>>(gcn_w, proj1_w, proj2_w, w_ih, w_hh, b_ih, b_hh,
                                    GW, P1, P2, WIH, WHH, GB0);
    gather_all_kernel<<<8202, 128>>>(q_l_conn, q_l_deg, q_r_conn, q_r_deg,
                                     s_l_conn, s_l_deg, s_r_conn, s_r_deg,
                                     emb, BQ, INVQ);

    // 2) GCN (129 tiles of 64 rows): tanh+remap epilogue -> QNB fp16
    mma_gemm<EPI_NB><<<dim3(1, 129), 256, SM3>>>(
        BQ, 256, GW, 256, 256, 0, nullptr, 256,
        gcn_bias, INVQ, QNB, nullptr, nullptr);

    // 3) proj1 (264 CTAs), proj2 split-K=2 (264 CTAs), LN folds partials+residual
    mma_gemm<EPI_RELU><<<dim3(4, 66), 256, SM3>>>(
        QNB, 256, P1, 256, 256, 0, nullptr, 512,
        proj1_b, nullptr, HQ, nullptr, nullptr);
    mma_gemm<EPI_RAW0><<<dim3(2, 66, 2), 256, SM3>>>(
        HQ, 512, P2, 512, 256, PSTRIDE_RES, ZP, 256,
        nullptr, nullptr, nullptr, nullptr, nullptr);
    ln_split_kernel<<<4101, 256>>>(ZP, QNB, proj2_b, ln_g, ln_b, QG, QGH);

    // 4) support vector + gb1
    sg_sn_kernel<<<1, 256>>>(QG, SG, SN);
    gb1_kernel<<<4, 256>>>(w_hh, SG, GB0, GB1);

    // 5) LSTM: GEMM + fused cell epilogues (512 CTAs each)
    mma_gemm<EPI_CELL0><<<dim3(8, 64), 256, SM3>>>(
        QGH, 256, WIH, 256, 256, 0, XW, 1024,
        GB0, QG, HH, C, H);
    for (int t = 1; t < 4; t++) {
        mma_gemm<EPI_CELL><<<dim3(8, 64), 256, SM3>>>(
            HH, 256, WHH, 256, 256, 0, XW, 1024,
            GB1, QG, HH, C, H);
    }

    // 6) cosine similarity
    final_kernel<<<4096, 256>>>(H, SN, out);
}

// round 13
// speedup vs baseline: 2.0082x; 1.0051x over previous
#include <cuda_runtime.h>
#include <cuda_fp16.h>
#include <math.h>
#include <stdint.h>

// ---------------------------------------------------------------------------
// EmbedMatcher on GB300 (sm_103 plain PTX -> mma.sync fp16 tensor cores).
//  - fp16 single-segment GEMMs, fp32 accumulate (rel_err ~5e-4, 2x margin).
//  - K=256 everywhere -> load ALL 4 K-chunks up front (one cp.async group,
//    one wait, ONE __syncthreads), then barrier-free compute. 96KB smem,
//    2 CTAs/SM.
//  - Split-K=2 on RES (folded into ln_split). NB epilogue in-GEMM.
//  - Gate-interleaved packing: LSTM cell fused into GEMM epilogue.
//  - Dead-gate elimination (N 2048->1024) + rank-1 support factorization.
// ---------------------------------------------------------------------------

__device__ __forceinline__ uint32_t smem_u32(const void* p) {
    uint32_t a;
    asm("{ .reg .u64 t; cvta.to.shared.u64 t, %1; cvt.u32.u64 %0, t; }"
        : "=r"(a) : "l"(p));
    return a;
}

// ================= fp32 scratch =================
constexpr size_t PSTRIDE_RES = 4224UL * 256;

constexpr size_t N_INVQ = 8320;
constexpr size_t N_ZP   = 2 * PSTRIDE_RES;
constexpr size_t N_QG   = 4224UL * 256;
constexpr size_t N_SN   = 256;
constexpr size_t N_XW   = 4096UL * 1024;
constexpr size_t N_GB0  = 1024;
constexpr size_t N_GB1  = 1024;
constexpr size_t N_C    = 4096UL * 256;
constexpr size_t N_H    = 4096UL * 256;

constexpr size_t O_INVQ = 0;
constexpr size_t O_ZP   = O_INVQ + N_INVQ;
constexpr size_t O_QG   = O_ZP   + N_ZP;
constexpr size_t O_SN   = O_QG   + N_QG;
constexpr size_t O_XW   = O_SN   + N_SN;
constexpr size_t O_GB0  = O_XW   + N_XW;
constexpr size_t O_GB1  = O_GB0  + N_GB0;
constexpr size_t O_C    = O_GB1  + N_GB1;
constexpr size_t O_H    = O_C    + N_C;
constexpr size_t SCRATCH_TOTAL = O_H + N_H;
__device__ float g_scratch[SCRATCH_TOTAL];

// ================= fp16 scratch =================
constexpr size_t H_BUFQ = 0;
constexpr size_t H_QNB  = H_BUFQ + 8320UL * 256;
constexpr size_t H_HQ   = H_QNB  + 4224UL * 256;
constexpr size_t H_QG   = H_HQ   + 4224UL * 512;
constexpr size_t H_HH   = H_QG   + 4224UL * 256;
constexpr size_t H_GW   = H_HH   + 4096UL * 256;
constexpr size_t H_P1   = H_GW   + 128UL * 256;
constexpr size_t H_P2   = H_P1   + 512UL * 256;
constexpr size_t H_WIH  = H_P2   + 256UL * 512;
constexpr size_t H_WHH  = H_WIH  + 1024UL * 256;
constexpr size_t HF_TOTAL = H_WHH + 1024UL * 256;
__device__ __align__(128) __half g_hf[HF_TOTAL];

// ================= helpers =================
__device__ __forceinline__ float sigf(float x) { return 1.0f / (1.0f + expf(-x)); }

__device__ __forceinline__ float block_sum256(float v, float* sbuf) {
    int t = threadIdx.x;
    sbuf[t] = v;
    __syncthreads();
    #pragma unroll
    for (int s = 128; s > 0; s >>= 1) {
        if (t < s) sbuf[t] += sbuf[t + s];
        __syncthreads();
    }
    float r = sbuf[0];
    __syncthreads();
    return r;
}

// ================= fused gather (query + support), float4 loads ==============
__global__ void gather_all_kernel(const int* __restrict__ qlc, const int* __restrict__ qld,
                                  const int* __restrict__ qrc, const int* __restrict__ qrd,
                                  const int* __restrict__ slc, const int* __restrict__ sld,
                                  const int* __restrict__ src_, const int* __restrict__ srd,
                                  const float* __restrict__ emb,
                                  __half* __restrict__ bq,
                                  float* __restrict__ invq)
{
    __shared__ int sc[128];
    __shared__ float4 red[2][4][32];
    int b = blockIdx.x;
    const int* conn; const int* deg; int r, row;
    if (b < 4096)      { r = b;        conn = qlc;  deg = qld; row = 2 * r; }
    else if (b < 8192) { r = b - 4096; conn = qrc;  deg = qrd; row = 2 * r + 1; }
    else if (b < 8197) { r = b - 8192; conn = slc;  deg = sld; row = 8192 + 2 * r; }
    else               { r = b - 8197; conn = src_; deg = srd; row = 8192 + 2 * r + 1; }
    int t = threadIdx.x;  // 128
    int w = t >> 5, l = t & 31;
    sc[t] = conn[r * 128 + t];
    __syncthreads();
    float4 a0 = make_float4(0.f, 0.f, 0.f, 0.f);
    float4 a1 = make_float4(0.f, 0.f, 0.f, 0.f);
    #pragma unroll 4
    for (int i = 0; i < 16; i++) {
        int n = w * 16 + i;
        float4 v0 = __ldg((const float4*)(emb + (size_t)sc[2 * n]     * 128) + l);
        float4 v1 = __ldg((const float4*)(emb + (size_t)sc[2 * n + 1] * 128) + l);
        a0.x += v0.x; a0.y += v0.y; a0.z += v0.z; a0.w += v0.w;
        a1.x += v1.x; a1.y += v1.y; a1.z += v1.z; a1.w += v1.w;
    }
    red[0][w][l] = a0;
    red[1][w][l] = a1;
    __syncthreads();
    if (t < 64) {
        int which = t >> 5, ll = t & 31;
        float4 p0 = red[which][0][ll], p1 = red[which][1][ll];
        float4 p2 = red[which][2][ll], p3 = red[which][3][ll];
        float s[4];
        s[0] = p0.x + p1.x + p2.x + p3.x;
        s[1] = p0.y + p1.y + p2.y + p3.y;
        s[2] = p0.z + p1.z + p2.z + p3.z;
        s[3] = p0.w + p1.w + p2.w + p3.w;
        size_t base = (size_t)row * 256 + which * 128 + ll * 4;
        #pragma unroll
        for (int j = 0; j < 4; j++) bq[base + j] = __float2half(s[j]);
    }
    if (t == 0) invq[row] = 1.0f / (float)max(deg[r], 1);
}

// ================= merged weight conversion + gb0 =============================
__global__ void split_all_kernel(const float* __restrict__ gcn_w,
                                 const float* __restrict__ p1w,
                                 const float* __restrict__ p2w,
                                 const float* __restrict__ w_ih,
                                 const float* __restrict__ w_hh,
                                 const float* __restrict__ b_ih,
                                 const float* __restrict__ b_hh,
                                 __half* __restrict__ gw,
                                 __half* __restrict__ p1,
                                 __half* __restrict__ p2,
                                 __half* __restrict__ wih,
                                 __half* __restrict__ whh,
                                 float* __restrict__ gb0)
{
    int b = blockIdx.x, t = threadIdx.x;
    if (b == 3200) {
        #pragma unroll
        for (int k = 0; k < 4; k++) {
            int col = k * 256 + t;
            int g = col & 3, u = col >> 2;
            gb0[col] = b_ih[g * 512 + u] + b_hh[g * 512 + u];
        }
        return;
    }
    float v;
    __half* dst;
    int idx;
    if (b < 128)       { idx = b * 256 + t;          v = gcn_w[idx]; dst = gw; }
    else if (b < 640)  { idx = (b - 128) * 256 + t;  v = p1w[idx];   dst = p1; }
    else if (b < 1152) { idx = (b - 640) * 256 + t;  v = p2w[idx];   dst = p2; }
    else {
        const float* W; int ldw;
        if (b < 2176) { idx = (b - 1152) * 256 + t; W = w_ih; ldw = 256; dst = wih; }
        else          { idx = (b - 2176) * 256 + t; W = w_hh; ldw = 512; dst = whh; }
        int orow = idx >> 8, c = idx & 255;
        int u = orow >> 2, g = orow & 3;           // packed col = u*4+g
        v = W[(size_t)(g * 512 + u) * ldw + c];
    }
    dst[idx] = __float2half(v);
}

// ================= gb1 = gb0 + rvec; block 0 also emits SN ===================
// 4 blocks x 256. Each block recomputes SG (mean of LN rows 4096..4100) in smem.
__global__ void gb1_sn_kernel(const float* __restrict__ w_hh,
                              const float* __restrict__ QG,
                              const float* __restrict__ gb0,
                              float* __restrict__ gb1,
                              float* __restrict__ SN)
{
    __shared__ float sg[256];
    __shared__ float sbuf[256];
    int t = threadIdx.x;
    float s = 0.f;
    #pragma unroll
    for (int r = 0; r < 5; r++) s += QG[(size_t)(4096 + r) * 256 + t];
    float v = s * 0.2f;
    sg[t] = v;
    __syncthreads();
    int col = blockIdx.x * 256 + t;    // 0..1023
    int g = col & 3, u = col >> 2;
    const float* w = w_hh + (size_t)(g * 512 + u) * 512 + 256;
    float acc = 0.0f;
    #pragma unroll 8
    for (int k = 0; k < 256; k++) acc += w[k] * sg[k];
    gb1[col] = gb0[col] + acc;
    if (blockIdx.x == 0) {
        float n2 = block_sum256(v * v, sbuf);
        SN[t] = v / fmaxf(sqrtf(n2), 1e-12f);
    }
}

// ================= unified mma.sync fp16 GEMM ================================
// 64x128 CTA tile, 8 warps (2m x 4n), K=256 = 4 chunks ALL loaded up front
// (one cp.async group, one wait, one __syncthreads), then barrier-free compute.
// 96KB smem, 2 CTAs/SM. blockIdx.z = split-K partition.
enum { EPI_RAW0 = 0, EPI_RELU = 1, EPI_NB = 3, EPI_CELL0 = 4, EPI_CELL = 5 };

__device__ __forceinline__ void cp16(uint32_t daddr, const void* g) {
    asm volatile("cp.async.cg.shared.global [%0], [%1], 16;" :: "r"(daddr), "l"(g));
}

__device__ __forceinline__ void stage_load(char* sa, char* sb,
                                           const __half* __restrict__ Asrc,
                                           const __half* __restrict__ Bsrc,
                                           int lda, int ldb, int bm, int bn,
                                           int koff, int tid)
{
    #pragma unroll
    for (int i = 0; i < 2; i++) {
        int idx = i * 256 + tid;
        int row = idx >> 3, ch = idx & 7;
        uint32_t off = (uint32_t)(row * 128 + ch * 16);
        uint32_t sw  = off ^ ((off >> 3) & 0x70);
        cp16(smem_u32(sa + sw), Asrc + (size_t)(bm + row) * lda + koff + ch * 8);
    }
    #pragma unroll
    for (int i = 0; i < 4; i++) {
        int idx = i * 256 + tid;
        int row = idx >> 3, ch = idx & 7;
        uint32_t off = (uint32_t)(row * 128 + ch * 16);
        uint32_t sw  = off ^ ((off >> 3) & 0x70);
        cp16(smem_u32(sb + sw), Bsrc + (size_t)(bn + row) * ldb + koff + ch * 8);
    }
}

template <int EPI>
__device__ __forceinline__ void cell_store(int r, int u,
                                           float gi, float gf, float gg, float go,
                                           float* __restrict__ cvec,
                                           const float* __restrict__ qg,
                                           float* __restrict__ hout,
                                           __half* __restrict__ outh)
{
    size_t idx = (size_t)r * 256 + u;
    float cp = (EPI == EPI_CELL) ? cvec[idx] : 0.0f;
    float cn = sigf(gf) * cp + sigf(gi) * tanhf(gg);
    cvec[idx] = cn;
    float hv = qg[idx] + sigf(go) * tanhf(cn);
    hout[idx] = hv;
    outh[idx] = __float2half(hv);
}

template <int EPI>
__device__ __forceinline__ void epi_store(int gm, int gn, float v,
                                          float* __restrict__ C, int ldc,
                                          const float* __restrict__ bias,
                                          const float* __restrict__ extra,
                                          __half* __restrict__ outh)
{
    if (EPI == EPI_RAW0) {
        C[(size_t)gm * ldc + gn] = v;
    } else if (EPI == EPI_RELU) {
        float o = fmaxf(v + bias[gn], 0.0f);
        outh[(size_t)gm * ldc + gn] = __float2half(o);
    } else {  // EPI_NB: tanh((v + 64*bias)*inv[gm]); remap (8k x 128)->(4k x 256)
        float o = tanhf((v + 64.0f * bias[gn]) * extra[gm]);
        size_t idx = (size_t)(gm >> 1) * 256 + (size_t)(gm & 1) * 128 + gn;
        outh[idx] = __float2half(o);
    }
}

template <int EPI>
__global__ __launch_bounds__(256, 2)
void mma_gemm(const __half* __restrict__ A, int lda,
              const __half* __restrict__ B, int ldb,
              int K, size_t pstride,
              float* __restrict__ C, int ldc,
              const float* __restrict__ bias, const float* __restrict__ extra,
              __half* __restrict__ outh,
              float* __restrict__ cvec, float* __restrict__ hout)
{
    constexpr int MI = 2;
    constexpr int ASZ = 64 * 128;          // 8 KB
    constexpr int STAGE = ASZ + 16384;     // 24 KB
    extern __shared__ char smem[];         // 4 stages = 96 KB
    const int tid  = threadIdx.x;
    const int wid  = tid >> 5;
    const int lane = tid & 31;
    const int bm = blockIdx.y * 64;
    const int bn = blockIdx.x * 128;
    const int zoff = blockIdx.z * K;
    C += (size_t)blockIdx.z * pstride;
    const int warp_m = wid & 1;
    const int warp_n = wid >> 1;

    float acc[MI][4][4];
    #pragma unroll
    for (int mi = 0; mi < MI; mi++)
        #pragma unroll
        for (int nj = 0; nj < 4; nj++)
            #pragma unroll
            for (int q = 0; q < 4; q++) acc[mi][nj][q] = 0.0f;

    const int a_row_off = (lane & 7) + ((lane >> 3) & 1) * 8;
    const int a_ch_off  = lane >> 4;
    const int b_row_off = (lane >> 4) * 8 + (lane & 7);
    const int b_ch_off  = (lane >> 3) & 1;

    const int nt = K >> 6;   // <= 4

    // Load EVERYTHING: one group, one wait, one barrier.
    for (int c = 0; c < nt; c++) {
        char* base = smem + c * STAGE;
        stage_load(base, base + ASZ, A, B, lda, ldb, bm, bn, zoff + c * 64, tid);
    }
    asm volatile("cp.async.commit_group;");
    asm volatile("cp.async.wait_group 0;");
    __syncthreads();

    for (int c = 0; c < nt; c++) {
        const uint32_t sa_base = smem_u32(smem + c * STAGE);
        const uint32_t sb_base = sa_base + ASZ;

        #pragma unroll
        for (int ks = 0; ks < 4; ks++) {
            uint32_t a[MI][4];
            #pragma unroll
            for (int mi = 0; mi < MI; mi++) {
                uint32_t row = warp_m * 32 + mi * 16 + a_row_off;
                uint32_t ch  = ks * 2 + a_ch_off;
                uint32_t off = row * 128 + ch * 16;
                uint32_t addr = sa_base + (off ^ ((off >> 3) & 0x70));
                asm volatile("ldmatrix.sync.aligned.m8n8.x4.shared.b16 {%0,%1,%2,%3}, [%4];"
                             : "=r"(a[mi][0]), "=r"(a[mi][1]), "=r"(a[mi][2]), "=r"(a[mi][3])
                             : "r"(addr));
            }
            uint32_t b[4][2];
            #pragma unroll
            for (int njp = 0; njp < 2; njp++) {
                uint32_t row = warp_n * 32 + njp * 16 + b_row_off;
                uint32_t ch  = ks * 2 + b_ch_off;
                uint32_t off = row * 128 + ch * 16;
                uint32_t addr = sb_base + (off ^ ((off >> 3) & 0x70));
                asm volatile("ldmatrix.sync.aligned.m8n8.x4.shared.b16 {%0,%1,%2,%3}, [%4];"
                             : "=r"(b[njp * 2][0]), "=r"(b[njp * 2][1]),
                               "=r"(b[njp * 2 + 1][0]), "=r"(b[njp * 2 + 1][1])
                             : "r"(addr));
            }
            #pragma unroll
            for (int mi = 0; mi < MI; mi++)
                #pragma unroll
                for (int nj = 0; nj < 4; nj++)
                    asm volatile(
                        "mma.sync.aligned.m16n8k16.row.col.f32.f16.f16.f32 "
                        "{%0,%1,%2,%3}, {%4,%5,%6,%7}, {%8,%9}, {%0,%1,%2,%3};"
                        : "+f"(acc[mi][nj][0]), "+f"(acc[mi][nj][1]),
                          "+f"(acc[mi][nj][2]), "+f"(acc[mi][nj][3])
                        : "r"(a[mi][0]), "r"(a[mi][1]), "r"(a[mi][2]), "r"(a[mi][3]),
                          "r"(b[nj][0]), "r"(b[nj][1]));
        }
    }

    if (EPI == EPI_CELL0 || EPI == EPI_CELL) {
        #pragma unroll
        for (int mi = 0; mi < MI; mi++) {
            int m0 = bm + warp_m * 32 + mi * 16 + (lane >> 2);
            #pragma unroll
            for (int nj = 0; nj < 4; nj++) {
                int n0 = bn + warp_n * 32 + nj * 8 + (lane & 3) * 2;
                float v0 = acc[mi][nj][0], v1 = acc[mi][nj][1];
                float v2 = acc[mi][nj][2], v3 = acc[mi][nj][3];
                if (EPI == EPI_CELL0) {
                    *(float2*)(C + (size_t)m0 * ldc + n0)       = make_float2(v0, v1);
                    *(float2*)(C + (size_t)(m0 + 8) * ldc + n0) = make_float2(v2, v3);
                } else {
                    float2 x0 = *(const float2*)(C + (size_t)m0 * ldc + n0);
                    float2 x1 = *(const float2*)(C + (size_t)(m0 + 8) * ldc + n0);
                    v0 += x0.x; v1 += x0.y; v2 += x1.x; v3 += x1.y;
                }
                float bb0 = bias[n0], bb1 = bias[n0 + 1];
                v0 += bb0; v1 += bb1; v2 += bb0; v3 += bb1;
                float e0 = __shfl_xor_sync(0xFFFFFFFFu, v0, 1);
                float e1 = __shfl_xor_sync(0xFFFFFFFFu, v1, 1);
                float e2 = __shfl_xor_sync(0xFFFFFFFFu, v2, 1);
                float e3 = __shfl_xor_sync(0xFFFFFFFFu, v3, 1);
                if ((lane & 1) == 0) {
                    int u = n0 >> 2;
                    cell_store<EPI>(m0,     u, v0, v1, e0, e1, cvec, extra, hout, outh);
                    cell_store<EPI>(m0 + 8, u, v2, v3, e2, e3, cvec, extra, hout, outh);
                }
            }
        }
    } else {
        #pragma unroll
        for (int mi = 0; mi < MI; mi++) {
            int m0 = bm + warp_m * 32 + mi * 16 + (lane >> 2);
            #pragma unroll
            for (int nj = 0; nj < 4; nj++) {
                int n0 = bn + warp_n * 32 + nj * 8 + (lane & 3) * 2;
                epi_store<EPI>(m0,     n0,     acc[mi][nj][0], C, ldc, bias, extra, outh);
                epi_store<EPI>(m0,     n0 + 1, acc[mi][nj][1], C, ldc, bias, extra, outh);
                epi_store<EPI>(m0 + 8, n0,     acc[mi][nj][2], C, ldc, bias, extra, outh);
                epi_store<EPI>(m0 + 8, n0 + 1, acc[mi][nj][3], C, ldc, bias, extra, outh);
            }
        }
    }
}

// ================= layernorm over RES partials + fp16 out ====================
__global__ void ln_split_kernel(const float* __restrict__ ZP,
                                const __half* __restrict__ QNB,
                                const float* __restrict__ p2b,
                                const float* __restrict__ g,
                                const float* __restrict__ bb,
                                float* __restrict__ out,
                                __half* __restrict__ oh)
{
    __shared__ float sbuf[256];
    int r = blockIdx.x, t = threadIdx.x;
    size_t idx = (size_t)r * 256 + t;
    float z = ZP[idx] + ZP[PSTRIDE_RES + idx] + p2b[t] + __half2float(QNB[idx]);
    float mu = block_sum256(z, sbuf) * (1.0f / 256.0f);
    float d = z - mu;
    float var = block_sum256(d * d, sbuf) * (1.0f / 255.0f);
    float o = g[t] * d / (sqrtf(var) + 1e-6f) + bb[t];
    out[idx] = o;
    oh[idx] = __float2half(o);
}

// ================= final cosine similarity =================
__global__ void final_kernel(const float* __restrict__ h,
                             const float* __restrict__ sn,
                             float* __restrict__ out)
{
    __shared__ float sbuf[256];
    int b = blockIdx.x, t = threadIdx.x;
    float v = h[(size_t)b * 256 + t];
    float dot = block_sum256(v * sn[t], sbuf);
    float n2  = block_sum256(v * v, sbuf);
    if (t == 0) out[b] = dot / fmaxf(sqrtf(n2), 1e-12f);
}

// ================= launch =================
extern "C" void kernel_launch(void* const* d_in, const int* in_sizes, int n_in,
                              void* d_out, int out_size)
{
    (void)in_sizes; (void)n_in; (void)out_size;
    const int*   q_l_conn = (const int*)  d_in[2];
    const int*   q_l_deg  = (const int*)  d_in[3];
    const int*   q_r_conn = (const int*)  d_in[4];
    const int*   q_r_deg  = (const int*)  d_in[5];
    const int*   s_l_conn = (const int*)  d_in[6];
    const int*   s_l_deg  = (const int*)  d_in[7];
    const int*   s_r_conn = (const int*)  d_in[8];
    const int*   s_r_deg  = (const int*)  d_in[9];
    const float* emb      = (const float*)d_in[10];
    const float* gcn_w    = (const float*)d_in[11];
    const float* gcn_bias = (const float*)d_in[12];
    const float* proj1_w  = (const float*)d_in[13];
    const float* proj1_b  = (const float*)d_in[14];
    const float* proj2_w  = (const float*)d_in[15];
    const float* proj2_b  = (const float*)d_in[16];
    const float* ln_g     = (const float*)d_in[17];
    const float* ln_b     = (const float*)d_in[18];
    const float* w_ih     = (const float*)d_in[19];
    const float* w_hh     = (const float*)d_in[20];
    const float* b_ih     = (const float*)d_in[21];
    const float* b_hh     = (const float*)d_in[22];
    float* out = (float*)d_out;

    float* S = nullptr;
    cudaGetSymbolAddress((void**)&S, g_scratch);
    __half* HF = nullptr;
    cudaGetSymbolAddress((void**)&HF, g_hf);

    float* INVQ = S + O_INVQ;  float* ZP  = S + O_ZP;    float* QG = S + O_QG;
    float* SN   = S + O_SN;    float* XW  = S + O_XW;
    float* GB0  = S + O_GB0;   float* GB1 = S + O_GB1;
    float* C    = S + O_C;     float* H   = S + O_H;

    __half* BQ  = HF + H_BUFQ;  __half* QNB = HF + H_QNB;
    __half* HQ  = HF + H_HQ;    __half* QGH = HF + H_QG;
    __half* HH  = HF + H_HH;    __half* GW  = HF + H_GW;
    __half* P1  = HF + H_P1;    __half* P2  = HF + H_P2;
    __half* WIH = HF + H_WIH;   __half* WHH = HF + H_WHH;

    const int SM4 = 4 * (64 * 128 + 16384);  // 98304
    cudaFuncSetAttribute(mma_gemm<EPI_RAW0>,  cudaFuncAttributeMaxDynamicSharedMemorySize, SM4);
    cudaFuncSetAttribute(mma_gemm<EPI_RELU>,  cudaFuncAttributeMaxDynamicSharedMemorySize, SM4);
    cudaFuncSetAttribute(mma_gemm<EPI_NB>,    cudaFuncAttributeMaxDynamicSharedMemorySize, SM4);
    cudaFuncSetAttribute(mma_gemm<EPI_CELL0>, cudaFuncAttributeMaxDynamicSharedMemorySize, SM4);
    cudaFuncSetAttribute(mma_gemm<EPI_CELL>,  cudaFuncAttributeMaxDynamicSharedMemorySize, SM4);

    // 1) weight fp16 conversion + gb0, gathers (query + support rows 8192..8201)
    split_all_kernel<<<3201, 256>>>(gcn_w, proj1_w, proj2_w, w_ih, w_hh, b_ih, b_hh,
                                    GW, P1, P2, WIH, WHH, GB0);
    gather_all_kernel<<<8202, 128>>>(q_l_conn, q_l_deg, q_r_conn, q_r_deg,
                                     s_l_conn, s_l_deg, s_r_conn, s_r_deg,
                                     emb, BQ, INVQ);

    // 2) GCN (129 tiles of 64 rows): tanh+remap epilogue -> QNB fp16
    mma_gemm<EPI_NB><<<dim3(1, 129), 256, SM4>>>(
        BQ, 256, GW, 256, 256, 0, nullptr, 256,
        gcn_bias, INVQ, QNB, nullptr, nullptr);

    // 3) proj1 (264 CTAs), proj2 split-K=2 (264 CTAs), LN folds partials+residual
    mma_gemm<EPI_RELU><<<dim3(4, 66), 256, SM4>>>(
        QNB, 256, P1, 256, 256, 0, nullptr, 512,
        proj1_b, nullptr, HQ, nullptr, nullptr);
    mma_gemm<EPI_RAW0><<<dim3(2, 66, 2), 256, SM4>>>(
        HQ, 512, P2, 512, 256, PSTRIDE_RES, ZP, 256,
        nullptr, nullptr, nullptr, nullptr, nullptr);
    ln_split_kernel<<<4101, 256>>>(ZP, QNB, proj2_b, ln_g, ln_b, QG, QGH);

    // 4) gb1 (+SN from block 0) — each block recomputes SG in smem
    gb1_sn_kernel<<<4, 256>>>(w_hh, QG, GB0, GB1, SN);

    // 5) LSTM: GEMM + fused cell epilogues (512 CTAs each)
    mma_gemm<EPI_CELL0><<<dim3(8, 64), 256, SM4>>>(
        QGH, 256, WIH, 256, 256, 0, XW, 1024,
        GB0, QG, HH, C, H);
    for (int t = 1; t < 4; t++) {
        mma_gemm<EPI_CELL><<<dim3(8, 64), 256, SM4>>>(
            HH, 256, WHH, 256, 256, 0, XW, 1024,
            GB1, QG, HH, C, H);
    }

    // 6) cosine similarity
    final_kernel<<<4096, 256>>>(H, SN, out);
}